// round 3
// baseline (speedup 1.0000x reference)
#include <cuda_runtime.h>
#include <cuda_bf16.h>
#include <math.h>

// Problem constants
#define B_ 4
#define N_ 2048
#define C_ 512
#define H_ 8
#define DH 64
#define M_ (B_ * N_)          // 8192
#define NQKV (3 * C_)         // 1536

// Scratch (device globals; no allocation allowed)
__device__ float g_Q[B_ * H_ * N_ * DH];
__device__ float g_K[B_ * H_ * N_ * DH];
__device__ float g_V[B_ * H_ * N_ * DH];
__device__ float g_O[B_ * N_ * C_];
__device__ float g_cos[B_ * N_ * (DH / 2)];
__device__ float g_sin[B_ * N_ * (DH / 2)];

// ---------------------------------------------------------------------------
// Kernel 0: RoPE cos/sin tables.  pos = rint(times*30); inv_freq = 10000^{-i/32}
// ---------------------------------------------------------------------------
__global__ void rope_table_kernel(const float* __restrict__ times) {
    int idx = blockIdx.x * 256 + threadIdx.x;
    if (idx >= B_ * N_ * 32) return;
    int i = idx & 31;
    int bn = idx >> 5;
    float pos = rintf(times[bn] * 30.0f);
    float inv_freq = powf(10000.0f, -(float)i / 32.0f);
    float f = pos * inv_freq;
    float s, c;
    sincosf(f, &s, &c);
    g_cos[idx] = c;
    g_sin[idx] = s;
}

// ---------------------------------------------------------------------------
// Kernel 1: QKV GEMM (M=8192, N=1536, K=512) + RoPE epilogue + scatter
//   out[m][n] = sum_k x[m][k] * Wqkv[n][k]
//   col n = s*512 + h*64 + d ;  s=0:q(rope), 1:k(rope), 2:v
//   BM=BN=128, BK=16, 256 threads, 8x8 micro-tile
// ---------------------------------------------------------------------------
__global__ __launch_bounds__(256) void gemm_qkv_kernel(const float* __restrict__ x,
                                                       const float* __restrict__ W) {
    __shared__ float As[16][132];
    __shared__ float Bs[16][132];
    int tid = threadIdx.x;
    int tx = tid & 15, ty = tid >> 4;
    int m0 = blockIdx.y * 128;
    int n0 = blockIdx.x * 128;
    int lr = tid >> 2;           // 0..63
    int lk = (tid & 3) << 2;     // 0,4,8,12

    float acc[8][8];
#pragma unroll
    for (int i = 0; i < 8; ++i)
#pragma unroll
        for (int j = 0; j < 8; ++j) acc[i][j] = 0.0f;

    for (int k0 = 0; k0 < 512; k0 += 16) {
        float4 a0 = *(const float4*)&x[(size_t)(m0 + lr) * 512 + k0 + lk];
        float4 a1 = *(const float4*)&x[(size_t)(m0 + lr + 64) * 512 + k0 + lk];
        float4 b0 = *(const float4*)&W[(size_t)(n0 + lr) * 512 + k0 + lk];
        float4 b1 = *(const float4*)&W[(size_t)(n0 + lr + 64) * 512 + k0 + lk];
        As[lk + 0][lr] = a0.x; As[lk + 1][lr] = a0.y; As[lk + 2][lr] = a0.z; As[lk + 3][lr] = a0.w;
        As[lk + 0][lr + 64] = a1.x; As[lk + 1][lr + 64] = a1.y; As[lk + 2][lr + 64] = a1.z; As[lk + 3][lr + 64] = a1.w;
        Bs[lk + 0][lr] = b0.x; Bs[lk + 1][lr] = b0.y; Bs[lk + 2][lr] = b0.z; Bs[lk + 3][lr] = b0.w;
        Bs[lk + 0][lr + 64] = b1.x; Bs[lk + 1][lr + 64] = b1.y; Bs[lk + 2][lr + 64] = b1.z; Bs[lk + 3][lr + 64] = b1.w;
        __syncthreads();
#pragma unroll
        for (int k = 0; k < 16; ++k) {
            float4 ra0 = *(const float4*)&As[k][ty * 8];
            float4 ra1 = *(const float4*)&As[k][ty * 8 + 4];
            float4 rb0 = *(const float4*)&Bs[k][tx * 4];
            float4 rb1 = *(const float4*)&Bs[k][tx * 4 + 64];
            float ra[8] = {ra0.x, ra0.y, ra0.z, ra0.w, ra1.x, ra1.y, ra1.z, ra1.w};
            float rb[8] = {rb0.x, rb0.y, rb0.z, rb0.w, rb1.x, rb1.y, rb1.z, rb1.w};
#pragma unroll
            for (int i = 0; i < 8; ++i)
#pragma unroll
                for (int j = 0; j < 8; ++j) acc[i][j] += ra[i] * rb[j];
        }
        __syncthreads();
    }

    // Epilogue: RoPE on q,k cols; scatter into [B,H,N,Dh]
#pragma unroll
    for (int i = 0; i < 8; ++i) {
        int m = m0 + ty * 8 + i;          // m = b*2048 + n
        int b = m >> 11;
        int n = m & 2047;
#pragma unroll
        for (int g = 0; g < 2; ++g) {
            int cb = n0 + tx * 4 + g * 64;    // 4 consecutive cols, pair-aligned
            int s = cb >> 9;
            int h = (cb >> 6) & 7;
            int d = cb & 63;
            size_t base = ((size_t)((b * 8 + h) * 2048 + n)) * 64 + d;
            float v0 = acc[i][g * 4 + 0];
            float v1 = acc[i][g * 4 + 1];
            float v2 = acc[i][g * 4 + 2];
            float v3 = acc[i][g * 4 + 3];
            if (s == 2) {
                g_V[base + 0] = v0; g_V[base + 1] = v1;
                g_V[base + 2] = v2; g_V[base + 3] = v3;
            } else {
                int i2 = d >> 1;
                float c0 = g_cos[m * 32 + i2],     s0 = g_sin[m * 32 + i2];
                float c1 = g_cos[m * 32 + i2 + 1], s1 = g_sin[m * 32 + i2 + 1];
                float* dst = (s == 0) ? g_Q : g_K;
                dst[base + 0] = v0 * c0 - v1 * s0;
                dst[base + 1] = v0 * s0 + v1 * c0;
                dst[base + 2] = v2 * c1 - v3 * s1;
                dst[base + 3] = v2 * s1 + v3 * c1;
            }
        }
    }
}

// ---------------------------------------------------------------------------
// Kernel 2: flash attention.  grid (32 q-tiles, 32 b*h), 256 threads.
// Q tile 64x64, loop over 32 KV tiles of 64. Online softmax.
// Ks buffer reused for P after S-compute. Dynamic smem = 51200 B.
// ---------------------------------------------------------------------------
__global__ __launch_bounds__(256) void attn_kernel(const float* __restrict__ mask) {
    extern __shared__ float sm[];
    float* Qs = sm;                 // 64*64   (stride 64, broadcast reads)
    float* Ks = sm + 4096;          // 64*68   (also P after exp)
    float* Vs = Ks + 64 * 68;       // 64*68

    int tid = threadIdx.x;
    int tx = tid & 15, ty = tid >> 4;
    int bh = blockIdx.y;
    int b = bh >> 3, h = bh & 7;
    int q0 = blockIdx.x * 64;

    const float* Qg = g_Q + ((size_t)bh * 2048 + q0) * 64;
    const float* Kgb = g_K + (size_t)bh * 2048 * 64;
    const float* Vgb = g_V + (size_t)bh * 2048 * 64;
    const float* maskb = mask + b * 2048;

    for (int idx = tid; idx < 4096; idx += 256) Qs[idx] = Qg[idx];

    float mi[4], li[4], acc[4][4];
#pragma unroll
    for (int i = 0; i < 4; ++i) {
        mi[i] = -INFINITY; li[i] = 0.0f;
#pragma unroll
        for (int j = 0; j < 4; ++j) acc[i][j] = 0.0f;
    }

    for (int kt = 0; kt < 32; ++kt) {
        __syncthreads();   // previous tile's P/V fully consumed
        for (int idx = tid; idx < 4096; idx += 256) {
            int r = idx >> 6, d = idx & 63;
            Ks[r * 68 + d] = Kgb[(size_t)(kt * 64 + r) * 64 + d];
            Vs[r * 68 + d] = Vgb[(size_t)(kt * 64 + r) * 64 + d];
        }
        __syncthreads();

        // S = Q K^T  (rows ty*4+i, kv-cols tx+16j)
        float s[4][4];
#pragma unroll
        for (int i = 0; i < 4; ++i)
#pragma unroll
            for (int j = 0; j < 4; ++j) s[i][j] = 0.0f;

#pragma unroll
        for (int k = 0; k < 64; k += 4) {
            float4 q[4], kr[4];
#pragma unroll
            for (int i = 0; i < 4; ++i) q[i] = *(const float4*)&Qs[(ty * 4 + i) * 64 + k];
#pragma unroll
            for (int j = 0; j < 4; ++j) kr[j] = *(const float4*)&Ks[(tx + 16 * j) * 68 + k];
#pragma unroll
            for (int i = 0; i < 4; ++i)
#pragma unroll
                for (int j = 0; j < 4; ++j) {
                    s[i][j] += q[i].x * kr[j].x;
                    s[i][j] += q[i].y * kr[j].y;
                    s[i][j] += q[i].z * kr[j].z;
                    s[i][j] += q[i].w * kr[j].w;
                }
        }

        // scale + mask, online softmax update
        float mk[4];
#pragma unroll
        for (int j = 0; j < 4; ++j) mk[j] = maskb[kt * 64 + tx + 16 * j];

        float p[4][4], corr[4], rs[4];
#pragma unroll
        for (int i = 0; i < 4; ++i) {
            float rm = -INFINITY;
#pragma unroll
            for (int j = 0; j < 4; ++j) {
                s[i][j] = s[i][j] * 0.125f + mk[j];
                rm = fmaxf(rm, s[i][j]);
            }
            // butterfly max across the 16 tx lanes
            rm = fmaxf(rm, __shfl_xor_sync(0xffffffffu, rm, 8));
            rm = fmaxf(rm, __shfl_xor_sync(0xffffffffu, rm, 4));
            rm = fmaxf(rm, __shfl_xor_sync(0xffffffffu, rm, 2));
            rm = fmaxf(rm, __shfl_xor_sync(0xffffffffu, rm, 1));
            float mnew = fmaxf(mi[i], rm);
            corr[i] = __expf(mi[i] - mnew);
            float sum = 0.0f;
#pragma unroll
            for (int j = 0; j < 4; ++j) {
                p[i][j] = __expf(s[i][j] - mnew);
                sum += p[i][j];
            }
            sum += __shfl_xor_sync(0xffffffffu, sum, 8);
            sum += __shfl_xor_sync(0xffffffffu, sum, 4);
            sum += __shfl_xor_sync(0xffffffffu, sum, 2);
            sum += __shfl_xor_sync(0xffffffffu, sum, 1);
            rs[i] = sum;
            mi[i] = mnew;
        }
#pragma unroll
        for (int i = 0; i < 4; ++i) {
            li[i] = li[i] * corr[i] + rs[i];
#pragma unroll
            for (int j = 0; j < 4; ++j) acc[i][j] *= corr[i];
        }

        __syncthreads();   // everyone done reading Ks
        // write P into the K buffer
#pragma unroll
        for (int i = 0; i < 4; ++i)
#pragma unroll
            for (int j = 0; j < 4; ++j)
                Ks[(ty * 4 + i) * 68 + tx + 16 * j] = p[i][j];
        __syncthreads();

        // O += P V  (Dh-cols tx+16j)
#pragma unroll
        for (int k = 0; k < 64; k += 4) {
            float4 pr[4];
#pragma unroll
            for (int i = 0; i < 4; ++i) pr[i] = *(const float4*)&Ks[(ty * 4 + i) * 68 + k];
#pragma unroll
            for (int kk = 0; kk < 4; ++kk) {
                float vv[4];
#pragma unroll
                for (int j = 0; j < 4; ++j) vv[j] = Vs[(k + kk) * 68 + tx + 16 * j];
                float pk[4] = { kk == 0 ? pr[0].x : kk == 1 ? pr[0].y : kk == 2 ? pr[0].z : pr[0].w,
                                kk == 0 ? pr[1].x : kk == 1 ? pr[1].y : kk == 2 ? pr[1].z : pr[1].w,
                                kk == 0 ? pr[2].x : kk == 1 ? pr[2].y : kk == 2 ? pr[2].z : pr[2].w,
                                kk == 0 ? pr[3].x : kk == 1 ? pr[3].y : kk == 2 ? pr[3].z : pr[3].w };
#pragma unroll
                for (int i = 0; i < 4; ++i)
#pragma unroll
                    for (int j = 0; j < 4; ++j) acc[i][j] += pk[i] * vv[j];
            }
        }
    }

    // normalize + write to g_O [B,N,C]
#pragma unroll
    for (int i = 0; i < 4; ++i) {
        float inv = 1.0f / li[i];
        int row = q0 + ty * 4 + i;
#pragma unroll
        for (int j = 0; j < 4; ++j) {
            g_O[((size_t)(b * 2048 + row)) * 512 + h * 64 + tx + 16 * j] = acc[i][j] * inv;
        }
    }
}

// ---------------------------------------------------------------------------
// Kernel 3: output projection (M=8192, N=512, K=512) + bias
// ---------------------------------------------------------------------------
__global__ __launch_bounds__(256) void gemm_proj_kernel(const float* __restrict__ W,
                                                        const float* __restrict__ bias,
                                                        float* __restrict__ out) {
    __shared__ float As[16][132];
    __shared__ float Bs[16][132];
    int tid = threadIdx.x;
    int tx = tid & 15, ty = tid >> 4;
    int m0 = blockIdx.y * 128;
    int n0 = blockIdx.x * 128;
    int lr = tid >> 2;
    int lk = (tid & 3) << 2;

    float acc[8][8];
#pragma unroll
    for (int i = 0; i < 8; ++i)
#pragma unroll
        for (int j = 0; j < 8; ++j) acc[i][j] = 0.0f;

    for (int k0 = 0; k0 < 512; k0 += 16) {
        float4 a0 = *(const float4*)&g_O[(size_t)(m0 + lr) * 512 + k0 + lk];
        float4 a1 = *(const float4*)&g_O[(size_t)(m0 + lr + 64) * 512 + k0 + lk];
        float4 b0 = *(const float4*)&W[(size_t)(n0 + lr) * 512 + k0 + lk];
        float4 b1 = *(const float4*)&W[(size_t)(n0 + lr + 64) * 512 + k0 + lk];
        As[lk + 0][lr] = a0.x; As[lk + 1][lr] = a0.y; As[lk + 2][lr] = a0.z; As[lk + 3][lr] = a0.w;
        As[lk + 0][lr + 64] = a1.x; As[lk + 1][lr + 64] = a1.y; As[lk + 2][lr + 64] = a1.z; As[lk + 3][lr + 64] = a1.w;
        Bs[lk + 0][lr] = b0.x; Bs[lk + 1][lr] = b0.y; Bs[lk + 2][lr] = b0.z; Bs[lk + 3][lr] = b0.w;
        Bs[lk + 0][lr + 64] = b1.x; Bs[lk + 1][lr + 64] = b1.y; Bs[lk + 2][lr + 64] = b1.z; Bs[lk + 3][lr + 64] = b1.w;
        __syncthreads();
#pragma unroll
        for (int k = 0; k < 16; ++k) {
            float4 ra0 = *(const float4*)&As[k][ty * 8];
            float4 ra1 = *(const float4*)&As[k][ty * 8 + 4];
            float4 rb0 = *(const float4*)&Bs[k][tx * 4];
            float4 rb1 = *(const float4*)&Bs[k][tx * 4 + 64];
            float ra[8] = {ra0.x, ra0.y, ra0.z, ra0.w, ra1.x, ra1.y, ra1.z, ra1.w};
            float rb[8] = {rb0.x, rb0.y, rb0.z, rb0.w, rb1.x, rb1.y, rb1.z, rb1.w};
#pragma unroll
            for (int i = 0; i < 8; ++i)
#pragma unroll
                for (int j = 0; j < 8; ++j) acc[i][j] += ra[i] * rb[j];
        }
        __syncthreads();
    }

#pragma unroll
    for (int i = 0; i < 8; ++i) {
        int m = m0 + ty * 8 + i;
#pragma unroll
        for (int g = 0; g < 2; ++g) {
            int cb = n0 + tx * 4 + g * 64;
            float4 bb = *(const float4*)&bias[cb];
            float4 o;
            o.x = acc[i][g * 4 + 0] + bb.x;
            o.y = acc[i][g * 4 + 1] + bb.y;
            o.z = acc[i][g * 4 + 2] + bb.z;
            o.w = acc[i][g * 4 + 3] + bb.w;
            *(float4*)&out[(size_t)m * 512 + cb] = o;
        }
    }
}

// ---------------------------------------------------------------------------
extern "C" void kernel_launch(void* const* d_in, const int* in_sizes, int n_in,
                              void* d_out, int out_size) {
    const float* x     = (const float*)d_in[0];
    const float* mask  = (const float*)d_in[1];
    const float* times = (const float*)d_in[2];
    const float* Wqkv  = (const float*)d_in[3];
    const float* Wproj = (const float*)d_in[4];
    const float* bproj = (const float*)d_in[5];
    (void)in_sizes; (void)n_in; (void)out_size;   // num_cls_token == 0 (fixed input)

    rope_table_kernel<<<(B_ * N_ * 32 + 255) / 256, 256>>>(times);
    gemm_qkv_kernel<<<dim3(NQKV / 128, M_ / 128), 256>>>(x, Wqkv);

    const int attn_smem = (4096 + 64 * 68 + 64 * 68) * sizeof(float);  // 51200
    cudaFuncSetAttribute(attn_kernel, cudaFuncAttributeMaxDynamicSharedMemorySize, attn_smem);
    attn_kernel<<<dim3(N_ / 64, B_ * H_), 256, attn_smem>>>(mask);

    gemm_proj_kernel<<<dim3(C_ / 128, M_ / 128), 256>>>(Wproj, bproj, (float*)d_out);
}

// round 4
// speedup vs baseline: 2.4254x; 2.4254x over previous
#include <cuda_runtime.h>
#include <cuda_bf16.h>
#include <math.h>
#include <stdint.h>

// Problem constants
#define B_ 4
#define N_ 2048
#define C_ 512
#define H_ 8
#define DH 64
#define M_ (B_ * N_)          // 8192
#define NQKV (3 * C_)         // 1536

// Scratch (device globals; no allocation allowed)
__device__ float g_Q[B_ * H_ * N_ * DH];
__device__ float g_K[B_ * H_ * N_ * DH];
__device__ float g_V[B_ * H_ * N_ * DH];
__device__ float g_O[B_ * N_ * C_];
__device__ float g_cos[B_ * N_ * (DH / 2)];
__device__ float g_sin[B_ * N_ * (DH / 2)];

// ---------------------------------------------------------------------------
// tf32 helpers
// ---------------------------------------------------------------------------
__device__ __forceinline__ float ftf(float x) {
    uint32_t u;
    asm("cvt.rna.tf32.f32 %0, %1;" : "=r"(u) : "f"(x));
    return __uint_as_float(u);
}

__device__ __forceinline__ void mma8(float* c,
                                     uint32_t a0, uint32_t a1, uint32_t a2, uint32_t a3,
                                     uint32_t b0, uint32_t b1) {
    asm volatile(
        "mma.sync.aligned.m16n8k8.row.col.f32.tf32.tf32.f32 "
        "{%0,%1,%2,%3},{%4,%5,%6,%7},{%8,%9},{%0,%1,%2,%3};"
        : "+f"(c[0]), "+f"(c[1]), "+f"(c[2]), "+f"(c[3])
        : "r"(a0), "r"(a1), "r"(a2), "r"(a3), "r"(b0), "r"(b1));
}

// ---------------------------------------------------------------------------
// Kernel 0: RoPE cos/sin tables.
// ---------------------------------------------------------------------------
__global__ void rope_table_kernel(const float* __restrict__ times) {
    int idx = blockIdx.x * 256 + threadIdx.x;
    if (idx >= B_ * N_ * 32) return;
    int i = idx & 31;
    int bn = idx >> 5;
    float pos = rintf(times[bn] * 30.0f);
    float inv_freq = powf(10000.0f, -(float)i / 32.0f);
    float f = pos * inv_freq;
    float s, c;
    sincosf(f, &s, &c);
    g_cos[idx] = c;
    g_sin[idx] = s;
}

// ---------------------------------------------------------------------------
// Kernel 1: QKV GEMM via tf32 mma (M=8192, N=1536, K=512) + RoPE + scatter
//   128x128 tile, BK=32, 8 warps as 2(m) x 4(n), warp tile 64x32.
// ---------------------------------------------------------------------------
__global__ __launch_bounds__(256) void gemm_qkv_mma(const float* __restrict__ x,
                                                    const float* __restrict__ W) {
    __shared__ float As[128][36];
    __shared__ float Bs[128][36];
    const uint32_t* Asu = (const uint32_t*)&As[0][0];
    const uint32_t* Bsu = (const uint32_t*)&Bs[0][0];

    int tid = threadIdx.x;
    int w = tid >> 5, lane = tid & 31;
    int lq = lane >> 2, lr = lane & 3;
    int wm = w & 1, wn = w >> 1;
    int m0 = blockIdx.y * 128;
    int n0 = blockIdx.x * 128;

    float c[16][4];
#pragma unroll
    for (int f = 0; f < 16; ++f)
#pragma unroll
        for (int i = 0; i < 4; ++i) c[f][i] = 0.0f;

    int lrow = tid >> 1;             // 0..127
    int lk = (tid & 1) * 16;         // 0 or 16

    for (int k0 = 0; k0 < 512; k0 += 32) {
#pragma unroll
        for (int i = 0; i < 4; ++i) {
            float4 av = *(const float4*)&x[(size_t)(m0 + lrow) * 512 + k0 + lk + 4 * i];
            float4 bv = *(const float4*)&W[(size_t)(n0 + lrow) * 512 + k0 + lk + 4 * i];
            float4 at = make_float4(ftf(av.x), ftf(av.y), ftf(av.z), ftf(av.w));
            float4 bt = make_float4(ftf(bv.x), ftf(bv.y), ftf(bv.z), ftf(bv.w));
            *(float4*)&As[lrow][lk + 4 * i] = at;
            *(float4*)&Bs[lrow][lk + 4 * i] = bt;
        }
        __syncthreads();

#pragma unroll
        for (int ks = 0; ks < 4; ++ks) {
            uint32_t a[4][4];
#pragma unroll
            for (int mf = 0; mf < 4; ++mf) {
                int ar = wm * 64 + mf * 16 + lq;
                a[mf][0] = Asu[ar * 36 + ks * 8 + lr];
                a[mf][1] = Asu[(ar + 8) * 36 + ks * 8 + lr];
                a[mf][2] = Asu[ar * 36 + ks * 8 + 4 + lr];
                a[mf][3] = Asu[(ar + 8) * 36 + ks * 8 + 4 + lr];
            }
#pragma unroll
            for (int nf = 0; nf < 4; ++nf) {
                int br = wn * 32 + nf * 8 + lq;
                uint32_t b0 = Bsu[br * 36 + ks * 8 + lr];
                uint32_t b1 = Bsu[br * 36 + ks * 8 + 4 + lr];
#pragma unroll
                for (int mf = 0; mf < 4; ++mf)
                    mma8(c[mf * 4 + nf], a[mf][0], a[mf][1], a[mf][2], a[mf][3], b0, b1);
            }
        }
        __syncthreads();
    }

    // RoPE epilogue + scatter to g_Q/g_K/g_V [B,H,N,Dh]
#pragma unroll
    for (int mf = 0; mf < 4; ++mf) {
#pragma unroll
        for (int half = 0; half < 2; ++half) {
            int m = m0 + wm * 64 + mf * 16 + lq + half * 8;   // global row
            int b = m >> 11;
            int n = m & 2047;
#pragma unroll
            for (int nf = 0; nf < 4; ++nf) {
                int col = n0 + wn * 32 + nf * 8 + 2 * lr;
                int s = col >> 9;
                int h = (col >> 6) & 7;
                int d = col & 63;
                size_t base = ((size_t)((b * 8 + h) * 2048 + n)) * 64 + d;
                float v0 = c[mf * 4 + nf][half * 2 + 0];
                float v1 = c[mf * 4 + nf][half * 2 + 1];
                if (s == 2) {
                    *(float2*)&g_V[base] = make_float2(v0, v1);
                } else {
                    int i2 = d >> 1;
                    float ct = g_cos[m * 32 + i2];
                    float st = g_sin[m * 32 + i2];
                    float* dst = (s == 0) ? g_Q : g_K;
                    *(float2*)&dst[base] = make_float2(v0 * ct - v1 * st,
                                                       v0 * st + v1 * ct);
                }
            }
        }
    }
}

// ---------------------------------------------------------------------------
// Kernel 2: flash attention via tf32 mma.
//   Q tile 128 x 64, KV tile 64, 8 warps; warp owns 16 q-rows.
//   grid (16 q-tiles, 32 b*h), 256 threads, dyn smem 105728 B.
// ---------------------------------------------------------------------------
__global__ __launch_bounds__(256, 2) void attn_mma_kernel(const float* __restrict__ mask) {
    extern __shared__ float sm[];
    float* Qs = sm;                     // 128 x 68
    float* Ks = Qs + 128 * 68;          // 64 x 68
    float* Vs = Ks + 64 * 68;           // 64 x 72
    float* Ps = Vs + 64 * 72;           // 128 x 68 (per-warp 16-row slices)
    float* Ms = Ps + 128 * 68;          // 64
    const uint32_t* Qsu = (const uint32_t*)Qs;
    const uint32_t* Ksu = (const uint32_t*)Ks;
    const uint32_t* Vsu = (const uint32_t*)Vs;

    int tid = threadIdx.x;
    int w = tid >> 5, lane = tid & 31;
    int lq = lane >> 2, lr = lane & 3;
    int bh = blockIdx.y;
    int b = bh >> 3, h = bh & 7;
    int q0 = blockIdx.x * 128;

    const float* Qg = g_Q + ((size_t)bh * 2048 + q0) * 64;
    const float* Kgb = g_K + (size_t)bh * 2048 * 64;
    const float* Vgb = g_V + (size_t)bh * 2048 * 64;
    const float* maskb = mask + b * 2048;

    // Load Q tile to smem (tf32)
    for (int idx = tid; idx < 128 * 16; idx += 256) {
        int r = idx >> 4, c4 = (idx & 15) << 2;
        float4 v = *(const float4*)&Qg[(size_t)r * 64 + c4];
        *(float4*)&Qs[r * 68 + c4] = make_float4(ftf(v.x), ftf(v.y), ftf(v.z), ftf(v.w));
    }

    float co[8][4];
#pragma unroll
    for (int nf = 0; nf < 8; ++nf)
#pragma unroll
        for (int i = 0; i < 4; ++i) co[nf][i] = 0.0f;
    float mi0 = -INFINITY, mi1 = -INFINITY, li0 = 0.0f, li1 = 0.0f;

    for (int kt = 0; kt < 32; ++kt) {
        __syncthreads();     // previous tile fully consumed
        for (int idx = tid; idx < 64 * 16; idx += 256) {
            int r = idx >> 4, c4 = (idx & 15) << 2;
            float4 kv = *(const float4*)&Kgb[(size_t)(kt * 64 + r) * 64 + c4];
            float4 vv = *(const float4*)&Vgb[(size_t)(kt * 64 + r) * 64 + c4];
            *(float4*)&Ks[r * 68 + c4] = make_float4(ftf(kv.x), ftf(kv.y), ftf(kv.z), ftf(kv.w));
            *(float4*)&Vs[r * 72 + c4] = make_float4(ftf(vv.x), ftf(vv.y), ftf(vv.z), ftf(vv.w));
        }
        if (tid < 64) Ms[tid] = maskb[kt * 64 + tid];
        __syncthreads();

        // S = Q K^T : warp rows w*16..+15, cols 0..63
        float cs[8][4];
#pragma unroll
        for (int nf = 0; nf < 8; ++nf)
#pragma unroll
            for (int i = 0; i < 4; ++i) cs[nf][i] = 0.0f;

        int arow = (w * 16 + lq) * 68;
#pragma unroll
        for (int ks = 0; ks < 8; ++ks) {
            uint32_t a0 = Qsu[arow + ks * 8 + lr];
            uint32_t a1 = Qsu[arow + 8 * 68 + ks * 8 + lr];
            uint32_t a2 = Qsu[arow + ks * 8 + 4 + lr];
            uint32_t a3 = Qsu[arow + 8 * 68 + ks * 8 + 4 + lr];
#pragma unroll
            for (int nf = 0; nf < 8; ++nf) {
                uint32_t b0 = Ksu[(nf * 8 + lq) * 68 + ks * 8 + lr];
                uint32_t b1 = Ksu[(nf * 8 + lq) * 68 + ks * 8 + 4 + lr];
                mma8(cs[nf], a0, a1, a2, a3, b0, b1);
            }
        }

        // scale + mask + online softmax
        float rm0 = -INFINITY, rm1 = -INFINITY;
#pragma unroll
        for (int nf = 0; nf < 8; ++nf) {
            float mk0 = Ms[nf * 8 + 2 * lr];
            float mk1 = Ms[nf * 8 + 2 * lr + 1];
            cs[nf][0] = cs[nf][0] * 0.125f + mk0;
            cs[nf][1] = cs[nf][1] * 0.125f + mk1;
            cs[nf][2] = cs[nf][2] * 0.125f + mk0;
            cs[nf][3] = cs[nf][3] * 0.125f + mk1;
            rm0 = fmaxf(rm0, fmaxf(cs[nf][0], cs[nf][1]));
            rm1 = fmaxf(rm1, fmaxf(cs[nf][2], cs[nf][3]));
        }
        rm0 = fmaxf(rm0, __shfl_xor_sync(0xffffffffu, rm0, 1));
        rm0 = fmaxf(rm0, __shfl_xor_sync(0xffffffffu, rm0, 2));
        rm1 = fmaxf(rm1, __shfl_xor_sync(0xffffffffu, rm1, 1));
        rm1 = fmaxf(rm1, __shfl_xor_sync(0xffffffffu, rm1, 2));

        float mn0 = fmaxf(mi0, rm0);
        float mn1 = fmaxf(mi1, rm1);
        float corr0 = __expf(mi0 - mn0);
        float corr1 = __expf(mi1 - mn1);
        float sum0 = 0.0f, sum1 = 0.0f;
#pragma unroll
        for (int nf = 0; nf < 8; ++nf) {
            cs[nf][0] = __expf(cs[nf][0] - mn0);
            cs[nf][1] = __expf(cs[nf][1] - mn0);
            cs[nf][2] = __expf(cs[nf][2] - mn1);
            cs[nf][3] = __expf(cs[nf][3] - mn1);
            sum0 += cs[nf][0] + cs[nf][1];
            sum1 += cs[nf][2] + cs[nf][3];
        }
        sum0 += __shfl_xor_sync(0xffffffffu, sum0, 1);
        sum0 += __shfl_xor_sync(0xffffffffu, sum0, 2);
        sum1 += __shfl_xor_sync(0xffffffffu, sum1, 1);
        sum1 += __shfl_xor_sync(0xffffffffu, sum1, 2);
        li0 = li0 * corr0 + sum0;
        li1 = li1 * corr1 + sum1;
        mi0 = mn0; mi1 = mn1;
#pragma unroll
        for (int nf = 0; nf < 8; ++nf) {
            co[nf][0] *= corr0; co[nf][1] *= corr0;
            co[nf][2] *= corr1; co[nf][3] *= corr1;
        }

        // write P (tf32) into per-warp slice of Ps
        float* Pw = Ps + w * 16 * 68;
#pragma unroll
        for (int nf = 0; nf < 8; ++nf) {
            *(float2*)&Pw[lq * 68 + nf * 8 + 2 * lr] =
                make_float2(ftf(cs[nf][0]), ftf(cs[nf][1]));
            *(float2*)&Pw[(lq + 8) * 68 + nf * 8 + 2 * lr] =
                make_float2(ftf(cs[nf][2]), ftf(cs[nf][3]));
        }
        __syncwarp();

        // O += P V
        const uint32_t* Pu = (const uint32_t*)(Ps + w * 16 * 68);
#pragma unroll
        for (int ks = 0; ks < 8; ++ks) {
            uint32_t pa0 = Pu[lq * 68 + ks * 8 + lr];
            uint32_t pa1 = Pu[(lq + 8) * 68 + ks * 8 + lr];
            uint32_t pa2 = Pu[lq * 68 + ks * 8 + 4 + lr];
            uint32_t pa3 = Pu[(lq + 8) * 68 + ks * 8 + 4 + lr];
#pragma unroll
            for (int nf = 0; nf < 8; ++nf) {
                uint32_t b0 = Vsu[(ks * 8 + lr) * 72 + nf * 8 + lq];
                uint32_t b1 = Vsu[(ks * 8 + 4 + lr) * 72 + nf * 8 + lq];
                mma8(co[nf], pa0, pa1, pa2, pa3, b0, b1);
            }
        }
    }

    // normalize + write to g_O [B,N,C]
    float inv0 = 1.0f / li0;
    float inv1 = 1.0f / li1;
    int m0g = q0 + w * 16 + lq;
    int m1g = m0g + 8;
#pragma unroll
    for (int nf = 0; nf < 8; ++nf) {
        int col = h * 64 + nf * 8 + 2 * lr;
        *(float2*)&g_O[((size_t)(b * 2048 + m0g)) * 512 + col] =
            make_float2(co[nf][0] * inv0, co[nf][1] * inv0);
        *(float2*)&g_O[((size_t)(b * 2048 + m1g)) * 512 + col] =
            make_float2(co[nf][2] * inv1, co[nf][3] * inv1);
    }
}

// ---------------------------------------------------------------------------
// Kernel 3: output projection via tf32 mma (M=8192, N=512, K=512) + bias
// ---------------------------------------------------------------------------
__global__ __launch_bounds__(256) void gemm_proj_mma(const float* __restrict__ W,
                                                     const float* __restrict__ bias,
                                                     float* __restrict__ out) {
    __shared__ float As[128][36];
    __shared__ float Bs[128][36];
    const uint32_t* Asu = (const uint32_t*)&As[0][0];
    const uint32_t* Bsu = (const uint32_t*)&Bs[0][0];

    int tid = threadIdx.x;
    int w = tid >> 5, lane = tid & 31;
    int lq = lane >> 2, lr = lane & 3;
    int wm = w & 1, wn = w >> 1;
    int m0 = blockIdx.y * 128;
    int n0 = blockIdx.x * 128;

    float c[16][4];
#pragma unroll
    for (int f = 0; f < 16; ++f)
#pragma unroll
        for (int i = 0; i < 4; ++i) c[f][i] = 0.0f;

    int lrow = tid >> 1;
    int lk = (tid & 1) * 16;

    for (int k0 = 0; k0 < 512; k0 += 32) {
#pragma unroll
        for (int i = 0; i < 4; ++i) {
            float4 av = *(const float4*)&g_O[(size_t)(m0 + lrow) * 512 + k0 + lk + 4 * i];
            float4 bv = *(const float4*)&W[(size_t)(n0 + lrow) * 512 + k0 + lk + 4 * i];
            float4 at = make_float4(ftf(av.x), ftf(av.y), ftf(av.z), ftf(av.w));
            float4 bt = make_float4(ftf(bv.x), ftf(bv.y), ftf(bv.z), ftf(bv.w));
            *(float4*)&As[lrow][lk + 4 * i] = at;
            *(float4*)&Bs[lrow][lk + 4 * i] = bt;
        }
        __syncthreads();

#pragma unroll
        for (int ks = 0; ks < 4; ++ks) {
            uint32_t a[4][4];
#pragma unroll
            for (int mf = 0; mf < 4; ++mf) {
                int ar = wm * 64 + mf * 16 + lq;
                a[mf][0] = Asu[ar * 36 + ks * 8 + lr];
                a[mf][1] = Asu[(ar + 8) * 36 + ks * 8 + lr];
                a[mf][2] = Asu[ar * 36 + ks * 8 + 4 + lr];
                a[mf][3] = Asu[(ar + 8) * 36 + ks * 8 + 4 + lr];
            }
#pragma unroll
            for (int nf = 0; nf < 4; ++nf) {
                int br = wn * 32 + nf * 8 + lq;
                uint32_t b0 = Bsu[br * 36 + ks * 8 + lr];
                uint32_t b1 = Bsu[br * 36 + ks * 8 + 4 + lr];
#pragma unroll
                for (int mf = 0; mf < 4; ++mf)
                    mma8(c[mf * 4 + nf], a[mf][0], a[mf][1], a[mf][2], a[mf][3], b0, b1);
            }
        }
        __syncthreads();
    }

#pragma unroll
    for (int mf = 0; mf < 4; ++mf) {
#pragma unroll
        for (int half = 0; half < 2; ++half) {
            int m = m0 + wm * 64 + mf * 16 + lq + half * 8;
#pragma unroll
            for (int nf = 0; nf < 4; ++nf) {
                int col = n0 + wn * 32 + nf * 8 + 2 * lr;
                float v0 = c[mf * 4 + nf][half * 2 + 0] + bias[col];
                float v1 = c[mf * 4 + nf][half * 2 + 1] + bias[col + 1];
                *(float2*)&out[(size_t)m * 512 + col] = make_float2(v0, v1);
            }
        }
    }
}

// ---------------------------------------------------------------------------
extern "C" void kernel_launch(void* const* d_in, const int* in_sizes, int n_in,
                              void* d_out, int out_size) {
    const float* x     = (const float*)d_in[0];
    const float* mask  = (const float*)d_in[1];
    const float* times = (const float*)d_in[2];
    const float* Wqkv  = (const float*)d_in[3];
    const float* Wproj = (const float*)d_in[4];
    const float* bproj = (const float*)d_in[5];
    (void)in_sizes; (void)n_in; (void)out_size;   // num_cls_token == 0 (fixed input)

    rope_table_kernel<<<(B_ * N_ * 32 + 255) / 256, 256>>>(times);
    gemm_qkv_mma<<<dim3(NQKV / 128, M_ / 128), 256>>>(x, Wqkv);

    const int attn_smem = (128 * 68 + 64 * 68 + 64 * 72 + 128 * 68 + 64) * sizeof(float);
    cudaFuncSetAttribute(attn_mma_kernel, cudaFuncAttributeMaxDynamicSharedMemorySize, attn_smem);
    attn_mma_kernel<<<dim3(N_ / 128, B_ * H_), 256, attn_smem>>>(mask);

    gemm_proj_mma<<<dim3(C_ / 128, M_ / 128), 256>>>(Wproj, bproj, (float*)d_out);
}

// round 5
// speedup vs baseline: 2.5585x; 1.0549x over previous
#include <cuda_runtime.h>
#include <cuda_bf16.h>
#include <math.h>
#include <stdint.h>

// Problem constants
#define B_ 4
#define N_ 2048
#define C_ 512
#define H_ 8
#define DH 64
#define M_ (B_ * N_)          // 8192
#define NQKV (3 * C_)         // 1536

// Scratch (device globals; no allocation allowed)
__device__ float g_Q[B_ * H_ * N_ * DH];
__device__ float g_K[B_ * H_ * N_ * DH];
__device__ float g_Vt[B_ * H_ * DH * N_];   // V transposed: [b,h,d,n]
__device__ float g_O[B_ * N_ * C_];
__device__ float g_cos[B_ * N_ * (DH / 2)];
__device__ float g_sin[B_ * N_ * (DH / 2)];

// ---------------------------------------------------------------------------
// helpers
// ---------------------------------------------------------------------------
__device__ __forceinline__ float ftf(float x) {
    uint32_t u;
    asm("cvt.rna.tf32.f32 %0, %1;" : "=r"(u) : "f"(x));
    return __uint_as_float(u);
}

__device__ __forceinline__ void mma8(float* c,
                                     uint32_t a0, uint32_t a1, uint32_t a2, uint32_t a3,
                                     uint32_t b0, uint32_t b1) {
    asm volatile(
        "mma.sync.aligned.m16n8k8.row.col.f32.tf32.tf32.f32 "
        "{%0,%1,%2,%3},{%4,%5,%6,%7},{%8,%9},{%0,%1,%2,%3};"
        : "+f"(c[0]), "+f"(c[1]), "+f"(c[2]), "+f"(c[3])
        : "r"(a0), "r"(a1), "r"(a2), "r"(a3), "r"(b0), "r"(b1));
}

// ldmatrix x4: four 8x8 b16 tiles == four 8x4 tf32 tiles. Thread t of each
// 8-thread group supplies one 16B row address.
__device__ __forceinline__ void ldsm4(uint32_t& r0, uint32_t& r1, uint32_t& r2, uint32_t& r3,
                                      uint32_t addr) {
    asm volatile("ldmatrix.sync.aligned.m8n8.x4.shared.b16 {%0,%1,%2,%3}, [%4];"
                 : "=r"(r0), "=r"(r1), "=r"(r2), "=r"(r3) : "r"(addr));
}

// ---------------------------------------------------------------------------
// Kernel 0: RoPE cos/sin tables.
// ---------------------------------------------------------------------------
__global__ void rope_table_kernel(const float* __restrict__ times) {
    int idx = blockIdx.x * 256 + threadIdx.x;
    if (idx >= B_ * N_ * 32) return;
    int i = idx & 31;
    int bn = idx >> 5;
    float pos = rintf(times[bn] * 30.0f);
    float inv_freq = powf(10000.0f, -(float)i / 32.0f);
    float f = pos * inv_freq;
    float s, c;
    sincosf(f, &s, &c);
    g_cos[idx] = c;
    g_sin[idx] = s;
}

// ---------------------------------------------------------------------------
// Kernel 1: QKV GEMM via tf32 mma + LDSM (M=8192, N=1536, K=512) + RoPE
//   128x128 tile, BK=32, 8 warps as 2(m) x 4(n), warp tile 64x32.
//   V written TRANSPOSED into g_Vt[b,h,d,n].
// ---------------------------------------------------------------------------
__global__ __launch_bounds__(256) void gemm_qkv_mma(const float* __restrict__ x,
                                                    const float* __restrict__ W) {
    __shared__ float As[128][36];
    __shared__ float Bs[128][36];

    int tid = threadIdx.x;
    int w = tid >> 5, lane = tid & 31;
    int lq = lane >> 2, lr = lane & 3;
    int wm = w & 1, wn = w >> 1;
    int m0 = blockIdx.y * 128;
    int n0 = blockIdx.x * 128;

    // LDSM base addresses (bytes, shared space)
    uint32_t asb = (uint32_t)__cvta_generic_to_shared(&As[0][0]);
    uint32_t bsb = (uint32_t)__cvta_generic_to_shared(&Bs[0][0]);
    // A frag: rows wm*64 + mf*16 + (lane&15), col-half lane>>4
    uint32_t a_addr = asb + ((wm * 64 + (lane & 15)) * 36 + (lane >> 4) * 4) * 4;
    // B frag pair p: rows wn*32 + p*16 + (lane>>4)*8 + (lane&7), col-half (lane>>3)&1
    uint32_t b_addr = bsb + ((wn * 32 + (lane >> 4) * 8 + (lane & 7)) * 36 + ((lane >> 3) & 1) * 4) * 4;

    float c[16][4];
#pragma unroll
    for (int f = 0; f < 16; ++f)
#pragma unroll
        for (int i = 0; i < 4; ++i) c[f][i] = 0.0f;

    int lrow = tid >> 1;             // 0..127
    int lk = (tid & 1) * 16;         // 0 or 16

    for (int k0 = 0; k0 < 512; k0 += 32) {
#pragma unroll
        for (int i = 0; i < 4; ++i) {
            float4 av = *(const float4*)&x[(size_t)(m0 + lrow) * 512 + k0 + lk + 4 * i];
            float4 bv = *(const float4*)&W[(size_t)(n0 + lrow) * 512 + k0 + lk + 4 * i];
            *(float4*)&As[lrow][lk + 4 * i] = make_float4(ftf(av.x), ftf(av.y), ftf(av.z), ftf(av.w));
            *(float4*)&Bs[lrow][lk + 4 * i] = make_float4(ftf(bv.x), ftf(bv.y), ftf(bv.z), ftf(bv.w));
        }
        __syncthreads();

#pragma unroll
        for (int ks = 0; ks < 4; ++ks) {
            uint32_t a[4][4];
#pragma unroll
            for (int mf = 0; mf < 4; ++mf)
                ldsm4(a[mf][0], a[mf][1], a[mf][2], a[mf][3],
                      a_addr + (mf * 16 * 36 + ks * 8) * 4);
#pragma unroll
            for (int p = 0; p < 2; ++p) {
                uint32_t b0, b1, b2, b3;
                ldsm4(b0, b1, b2, b3, b_addr + (p * 16 * 36 + ks * 8) * 4);
#pragma unroll
                for (int mf = 0; mf < 4; ++mf) {
                    mma8(c[mf * 4 + 2 * p],     a[mf][0], a[mf][1], a[mf][2], a[mf][3], b0, b1);
                    mma8(c[mf * 4 + 2 * p + 1], a[mf][0], a[mf][1], a[mf][2], a[mf][3], b2, b3);
                }
            }
        }
        __syncthreads();
    }

    // RoPE epilogue + scatter; V goes transposed to g_Vt[b,h,d,n]
#pragma unroll
    for (int mf = 0; mf < 4; ++mf) {
#pragma unroll
        for (int half = 0; half < 2; ++half) {
            int m = m0 + wm * 64 + mf * 16 + lq + half * 8;   // global row
            int b = m >> 11;
            int n = m & 2047;
#pragma unroll
            for (int nf = 0; nf < 4; ++nf) {
                int col = n0 + wn * 32 + nf * 8 + 2 * lr;
                int s = col >> 9;
                int h = (col >> 6) & 7;
                int d = col & 63;
                float v0 = c[mf * 4 + nf][half * 2 + 0];
                float v1 = c[mf * 4 + nf][half * 2 + 1];
                if (s == 2) {
                    size_t vb = ((size_t)((b * 8 + h) * 64 + d)) * 2048 + n;
                    g_Vt[vb] = v0;
                    g_Vt[vb + 2048] = v1;
                } else {
                    size_t base = ((size_t)((b * 8 + h) * 2048 + n)) * 64 + d;
                    int i2 = d >> 1;
                    float ct = g_cos[m * 32 + i2];
                    float st = g_sin[m * 32 + i2];
                    float* dst = (s == 0) ? g_Q : g_K;
                    *(float2*)&dst[base] = make_float2(v0 * ct - v1 * st,
                                                       v0 * st + v1 * ct);
                }
            }
        }
    }
}

// ---------------------------------------------------------------------------
// Kernel 2: flash attention via tf32 mma + LDSM.
//   Q tile 128 x 64, KV tile 64, 8 warps; warp owns 16 q-rows.
//   grid (16 q-tiles, 32 b*h), 256 threads.
// ---------------------------------------------------------------------------
__global__ __launch_bounds__(256, 2) void attn_mma_kernel(const float* __restrict__ mask) {
    extern __shared__ float sm[];
    float* Qs = sm;                     // 128 x 68
    float* Ks = Qs + 128 * 68;          // 64 x 68   [kv][k]
    float* Vts = Ks + 64 * 68;          // 64 x 68   [d][kv]
    float* Ps = Vts + 64 * 68;          // 128 x 68  (per-warp 16-row slices)
    float* Ms = Ps + 128 * 68;          // 64

    int tid = threadIdx.x;
    int w = tid >> 5, lane = tid & 31;
    int lq = lane >> 2, lr = lane & 3;
    int bh = blockIdx.y;
    int b = bh >> 3, h = bh & 7;
    int q0 = blockIdx.x * 128;

    const float* Qg = g_Q + ((size_t)bh * 2048 + q0) * 64;
    const float* Kgb = g_K + (size_t)bh * 2048 * 64;
    const float* Vgb = g_Vt + (size_t)bh * 64 * 2048;
    const float* maskb = mask + b * 2048;

    // LDSM per-thread base addresses
    uint32_t qsb = (uint32_t)__cvta_generic_to_shared(Qs);
    uint32_t ksb = (uint32_t)__cvta_generic_to_shared(Ks);
    uint32_t vsb = (uint32_t)__cvta_generic_to_shared(Vts);
    uint32_t psb = (uint32_t)__cvta_generic_to_shared(Ps);
    // A-type (Q/P): rows base + (lane&15), col-half lane>>4
    uint32_t q_addr = qsb + ((w * 16 + (lane & 15)) * 68 + (lane >> 4) * 4) * 4;
    uint32_t p_addr = psb + ((w * 16 + (lane & 15)) * 68 + (lane >> 4) * 4) * 4;
    // B-type (K/Vt): pair p covers rows p*16 + (lane>>4)*8 + (lane&7), col-half (lane>>3)&1
    uint32_t kb_off = (((lane >> 4) * 8 + (lane & 7)) * 68 + ((lane >> 3) & 1) * 4) * 4;
    uint32_t k_addr = ksb + kb_off;
    uint32_t v_addr = vsb + kb_off;

    // Load Q tile to smem (tf32)
    for (int idx = tid; idx < 128 * 16; idx += 256) {
        int r = idx >> 4, c4 = (idx & 15) << 2;
        float4 v = *(const float4*)&Qg[(size_t)r * 64 + c4];
        *(float4*)&Qs[r * 68 + c4] = make_float4(ftf(v.x), ftf(v.y), ftf(v.z), ftf(v.w));
    }

    float co[8][4];
#pragma unroll
    for (int nf = 0; nf < 8; ++nf)
#pragma unroll
        for (int i = 0; i < 4; ++i) co[nf][i] = 0.0f;
    float mi0 = -INFINITY, mi1 = -INFINITY, li0 = 0.0f, li1 = 0.0f;

    for (int kt = 0; kt < 32; ++kt) {
        __syncthreads();     // previous tile fully consumed
        for (int idx = tid; idx < 64 * 16; idx += 256) {
            int r = idx >> 4, c4 = (idx & 15) << 2;
            float4 kv = *(const float4*)&Kgb[(size_t)(kt * 64 + r) * 64 + c4];
            float4 vv = *(const float4*)&Vgb[(size_t)r * 2048 + kt * 64 + c4];
            *(float4*)&Ks[r * 68 + c4]  = make_float4(ftf(kv.x), ftf(kv.y), ftf(kv.z), ftf(kv.w));
            *(float4*)&Vts[r * 68 + c4] = make_float4(ftf(vv.x), ftf(vv.y), ftf(vv.z), ftf(vv.w));
        }
        if (tid < 64) Ms[tid] = maskb[kt * 64 + tid];
        __syncthreads();

        // S = Q K^T : warp rows w*16..+15, cols 0..63
        float cs[8][4];
#pragma unroll
        for (int nf = 0; nf < 8; ++nf)
#pragma unroll
            for (int i = 0; i < 4; ++i) cs[nf][i] = 0.0f;

#pragma unroll
        for (int ks = 0; ks < 8; ++ks) {
            uint32_t a0, a1, a2, a3;
            ldsm4(a0, a1, a2, a3, q_addr + ks * 32);
#pragma unroll
            for (int p = 0; p < 4; ++p) {
                uint32_t b0, b1, b2, b3;
                ldsm4(b0, b1, b2, b3, k_addr + (p * 16 * 68) * 4 + ks * 32);
                mma8(cs[2 * p],     a0, a1, a2, a3, b0, b1);
                mma8(cs[2 * p + 1], a0, a1, a2, a3, b2, b3);
            }
        }

        // scale + mask + online softmax
        float rm0 = -INFINITY, rm1 = -INFINITY;
#pragma unroll
        for (int nf = 0; nf < 8; ++nf) {
            float mk0 = Ms[nf * 8 + 2 * lr];
            float mk1 = Ms[nf * 8 + 2 * lr + 1];
            cs[nf][0] = cs[nf][0] * 0.125f + mk0;
            cs[nf][1] = cs[nf][1] * 0.125f + mk1;
            cs[nf][2] = cs[nf][2] * 0.125f + mk0;
            cs[nf][3] = cs[nf][3] * 0.125f + mk1;
            rm0 = fmaxf(rm0, fmaxf(cs[nf][0], cs[nf][1]));
            rm1 = fmaxf(rm1, fmaxf(cs[nf][2], cs[nf][3]));
        }
        rm0 = fmaxf(rm0, __shfl_xor_sync(0xffffffffu, rm0, 1));
        rm0 = fmaxf(rm0, __shfl_xor_sync(0xffffffffu, rm0, 2));
        rm1 = fmaxf(rm1, __shfl_xor_sync(0xffffffffu, rm1, 1));
        rm1 = fmaxf(rm1, __shfl_xor_sync(0xffffffffu, rm1, 2));

        float mn0 = fmaxf(mi0, rm0);
        float mn1 = fmaxf(mi1, rm1);
        float corr0 = __expf(mi0 - mn0);
        float corr1 = __expf(mi1 - mn1);
        float sum0 = 0.0f, sum1 = 0.0f;
#pragma unroll
        for (int nf = 0; nf < 8; ++nf) {
            cs[nf][0] = __expf(cs[nf][0] - mn0);
            cs[nf][1] = __expf(cs[nf][1] - mn0);
            cs[nf][2] = __expf(cs[nf][2] - mn1);
            cs[nf][3] = __expf(cs[nf][3] - mn1);
            sum0 += cs[nf][0] + cs[nf][1];
            sum1 += cs[nf][2] + cs[nf][3];
        }
        sum0 += __shfl_xor_sync(0xffffffffu, sum0, 1);
        sum0 += __shfl_xor_sync(0xffffffffu, sum0, 2);
        sum1 += __shfl_xor_sync(0xffffffffu, sum1, 1);
        sum1 += __shfl_xor_sync(0xffffffffu, sum1, 2);
        li0 = li0 * corr0 + sum0;
        li1 = li1 * corr1 + sum1;
        mi0 = mn0; mi1 = mn1;
#pragma unroll
        for (int nf = 0; nf < 8; ++nf) {
            co[nf][0] *= corr0; co[nf][1] *= corr0;
            co[nf][2] *= corr1; co[nf][3] *= corr1;
        }

        // write P (tf32) into per-warp slice of Ps
        float* Pw = Ps + w * 16 * 68;
#pragma unroll
        for (int nf = 0; nf < 8; ++nf) {
            *(float2*)&Pw[lq * 68 + nf * 8 + 2 * lr] =
                make_float2(ftf(cs[nf][0]), ftf(cs[nf][1]));
            *(float2*)&Pw[(lq + 8) * 68 + nf * 8 + 2 * lr] =
                make_float2(ftf(cs[nf][2]), ftf(cs[nf][3]));
        }
        __syncwarp();

        // O += P V   (B-fragments straight from transposed V tile)
#pragma unroll
        for (int ks = 0; ks < 8; ++ks) {
            uint32_t pa0, pa1, pa2, pa3;
            ldsm4(pa0, pa1, pa2, pa3, p_addr + ks * 32);
#pragma unroll
            for (int p = 0; p < 4; ++p) {
                uint32_t b0, b1, b2, b3;
                ldsm4(b0, b1, b2, b3, v_addr + (p * 16 * 68) * 4 + ks * 32);
                mma8(co[2 * p],     pa0, pa1, pa2, pa3, b0, b1);
                mma8(co[2 * p + 1], pa0, pa1, pa2, pa3, b2, b3);
            }
        }
    }

    // normalize + write to g_O [B,N,C]
    float inv0 = 1.0f / li0;
    float inv1 = 1.0f / li1;
    int m0g = q0 + w * 16 + lq;
    int m1g = m0g + 8;
#pragma unroll
    for (int nf = 0; nf < 8; ++nf) {
        int col = h * 64 + nf * 8 + 2 * lr;
        *(float2*)&g_O[((size_t)(b * 2048 + m0g)) * 512 + col] =
            make_float2(co[nf][0] * inv0, co[nf][1] * inv0);
        *(float2*)&g_O[((size_t)(b * 2048 + m1g)) * 512 + col] =
            make_float2(co[nf][2] * inv1, co[nf][3] * inv1);
    }
}

// ---------------------------------------------------------------------------
// Kernel 3: output projection via tf32 mma + LDSM (M=8192, N=512, K=512)
// ---------------------------------------------------------------------------
__global__ __launch_bounds__(256) void gemm_proj_mma(const float* __restrict__ W,
                                                     const float* __restrict__ bias,
                                                     float* __restrict__ out) {
    __shared__ float As[128][36];
    __shared__ float Bs[128][36];

    int tid = threadIdx.x;
    int w = tid >> 5, lane = tid & 31;
    int lq = lane >> 2, lr = lane & 3;
    int wm = w & 1, wn = w >> 1;
    int m0 = blockIdx.y * 128;
    int n0 = blockIdx.x * 128;

    uint32_t asb = (uint32_t)__cvta_generic_to_shared(&As[0][0]);
    uint32_t bsb = (uint32_t)__cvta_generic_to_shared(&Bs[0][0]);
    uint32_t a_addr = asb + ((wm * 64 + (lane & 15)) * 36 + (lane >> 4) * 4) * 4;
    uint32_t b_addr = bsb + ((wn * 32 + (lane >> 4) * 8 + (lane & 7)) * 36 + ((lane >> 3) & 1) * 4) * 4;

    float c[16][4];
#pragma unroll
    for (int f = 0; f < 16; ++f)
#pragma unroll
        for (int i = 0; i < 4; ++i) c[f][i] = 0.0f;

    int lrow = tid >> 1;
    int lk = (tid & 1) * 16;

    for (int k0 = 0; k0 < 512; k0 += 32) {
#pragma unroll
        for (int i = 0; i < 4; ++i) {
            float4 av = *(const float4*)&g_O[(size_t)(m0 + lrow) * 512 + k0 + lk + 4 * i];
            float4 bv = *(const float4*)&W[(size_t)(n0 + lrow) * 512 + k0 + lk + 4 * i];
            *(float4*)&As[lrow][lk + 4 * i] = make_float4(ftf(av.x), ftf(av.y), ftf(av.z), ftf(av.w));
            *(float4*)&Bs[lrow][lk + 4 * i] = make_float4(ftf(bv.x), ftf(bv.y), ftf(bv.z), ftf(bv.w));
        }
        __syncthreads();

#pragma unroll
        for (int ks = 0; ks < 4; ++ks) {
            uint32_t a[4][4];
#pragma unroll
            for (int mf = 0; mf < 4; ++mf)
                ldsm4(a[mf][0], a[mf][1], a[mf][2], a[mf][3],
                      a_addr + (mf * 16 * 36 + ks * 8) * 4);
#pragma unroll
            for (int p = 0; p < 2; ++p) {
                uint32_t b0, b1, b2, b3;
                ldsm4(b0, b1, b2, b3, b_addr + (p * 16 * 36 + ks * 8) * 4);
#pragma unroll
                for (int mf = 0; mf < 4; ++mf) {
                    mma8(c[mf * 4 + 2 * p],     a[mf][0], a[mf][1], a[mf][2], a[mf][3], b0, b1);
                    mma8(c[mf * 4 + 2 * p + 1], a[mf][0], a[mf][1], a[mf][2], a[mf][3], b2, b3);
                }
            }
        }
        __syncthreads();
    }

#pragma unroll
    for (int mf = 0; mf < 4; ++mf) {
#pragma unroll
        for (int half = 0; half < 2; ++half) {
            int m = m0 + wm * 64 + mf * 16 + lq + half * 8;
#pragma unroll
            for (int nf = 0; nf < 4; ++nf) {
                int col = n0 + wn * 32 + nf * 8 + 2 * lr;
                float v0 = c[mf * 4 + nf][half * 2 + 0] + bias[col];
                float v1 = c[mf * 4 + nf][half * 2 + 1] + bias[col + 1];
                *(float2*)&out[(size_t)m * 512 + col] = make_float2(v0, v1);
            }
        }
    }
}

// ---------------------------------------------------------------------------
extern "C" void kernel_launch(void* const* d_in, const int* in_sizes, int n_in,
                              void* d_out, int out_size) {
    const float* x     = (const float*)d_in[0];
    const float* mask  = (const float*)d_in[1];
    const float* times = (const float*)d_in[2];
    const float* Wqkv  = (const float*)d_in[3];
    const float* Wproj = (const float*)d_in[4];
    const float* bproj = (const float*)d_in[5];
    (void)in_sizes; (void)n_in; (void)out_size;   // num_cls_token == 0 (fixed input)

    rope_table_kernel<<<(B_ * N_ * 32 + 255) / 256, 256>>>(times);
    gemm_qkv_mma<<<dim3(NQKV / 128, M_ / 128), 256>>>(x, Wqkv);

    const int attn_smem = (128 * 68 + 64 * 68 + 64 * 68 + 128 * 68 + 64) * sizeof(float);
    cudaFuncSetAttribute(attn_mma_kernel, cudaFuncAttributeMaxDynamicSharedMemorySize, attn_smem);
    attn_mma_kernel<<<dim3(N_ / 128, B_ * H_), 256, attn_smem>>>(mask);

    gemm_proj_mma<<<dim3(C_ / 128, M_ / 128), 256>>>(Wproj, bproj, (float*)d_out);
}

// round 6
// speedup vs baseline: 5.2380x; 2.0473x over previous
#include <cuda_runtime.h>
#include <cuda_fp16.h>
#include <math.h>
#include <stdint.h>

// Problem constants
#define B_ 4
#define N_ 2048
#define C_ 512
#define H_ 8
#define DH 64
#define M_ (B_ * N_)          // 8192
#define NQKV (3 * C_)         // 1536

// Scratch (device globals; no allocation allowed)
__device__ __half g_xh[M_ * C_];
__device__ __half g_Wqkvh[NQKV * C_];
__device__ __half g_Wprojh[C_ * C_];
__device__ __half g_Qh[B_ * H_ * N_ * DH];
__device__ __half g_Kh[B_ * H_ * N_ * DH];
__device__ __half g_Vth[B_ * H_ * DH * N_];   // V transposed: [b,h,d,n]
__device__ __half g_Oh[M_ * C_];
__device__ float g_cos[B_ * N_ * (DH / 2)];
__device__ float g_sin[B_ * N_ * (DH / 2)];

// ---------------------------------------------------------------------------
// helpers
// ---------------------------------------------------------------------------
__device__ __forceinline__ void mma16(float* c,
                                      uint32_t a0, uint32_t a1, uint32_t a2, uint32_t a3,
                                      uint32_t b0, uint32_t b1) {
    asm volatile(
        "mma.sync.aligned.m16n8k16.row.col.f32.f16.f16.f32 "
        "{%0,%1,%2,%3},{%4,%5,%6,%7},{%8,%9},{%0,%1,%2,%3};"
        : "+f"(c[0]), "+f"(c[1]), "+f"(c[2]), "+f"(c[3])
        : "r"(a0), "r"(a1), "r"(a2), "r"(a3), "r"(b0), "r"(b1));
}

__device__ __forceinline__ void ldsm4(uint32_t& r0, uint32_t& r1, uint32_t& r2, uint32_t& r3,
                                      uint32_t addr) {
    asm volatile("ldmatrix.sync.aligned.m8n8.x4.shared.b16 {%0,%1,%2,%3}, [%4];"
                 : "=r"(r0), "=r"(r1), "=r"(r2), "=r"(r3) : "r"(addr));
}

__device__ __forceinline__ void cp16(uint32_t dst, const void* src) {
    asm volatile("cp.async.cg.shared.global [%0], [%1], 16;" :: "r"(dst), "l"(src));
}
#define CP_COMMIT() asm volatile("cp.async.commit_group;")
#define CP_WAIT0()  asm volatile("cp.async.wait_group 0;")

__device__ __forceinline__ uint32_t pack2(float lo, float hi) {
    __half2 t = __floats2half2_rn(lo, hi);
    return *reinterpret_cast<uint32_t*>(&t);
}

// ---------------------------------------------------------------------------
// Kernel: fp32 -> fp16 conversion (vectorized)
// ---------------------------------------------------------------------------
__global__ void f2h_kernel(const float* __restrict__ in, __half* __restrict__ out, int n4) {
    int i = blockIdx.x * 256 + threadIdx.x;
    if (i >= n4) return;
    float4 v = ((const float4*)in)[i];
    __half2* o = (__half2*)out;
    o[2 * i]     = __floats2half2_rn(v.x, v.y);
    o[2 * i + 1] = __floats2half2_rn(v.z, v.w);
}

// ---------------------------------------------------------------------------
// Kernel 0: RoPE cos/sin tables.
// ---------------------------------------------------------------------------
__global__ void rope_table_kernel(const float* __restrict__ times) {
    int idx = blockIdx.x * 256 + threadIdx.x;
    if (idx >= B_ * N_ * 32) return;
    int i = idx & 31;
    int bn = idx >> 5;
    float pos = rintf(times[bn] * 30.0f);
    float inv_freq = powf(10000.0f, -(float)i / 32.0f);
    float f = pos * inv_freq;
    float s, c;
    sincosf(f, &s, &c);
    g_cos[idx] = c;
    g_sin[idx] = s;
}

// ---------------------------------------------------------------------------
// Kernel 1: QKV GEMM fp16 mma (M=8192, N=1536, K=512) + RoPE + scatter
//   128x128 tile, BK=32, 8 warps as 2(m) x 4(n), double-buffered cp.async.
// ---------------------------------------------------------------------------
__global__ __launch_bounds__(256) void gemm_qkv_h() {
    __shared__ __half As[2][128 * 40];
    __shared__ __half Bs[2][128 * 40];

    int tid = threadIdx.x;
    int w = tid >> 5, lane = tid & 31;
    int lq = lane >> 2, lr = lane & 3;
    int wm = w & 1, wn = w >> 1;
    int m0 = blockIdx.y * 128;
    int n0 = blockIdx.x * 128;

    int lrow = tid >> 1;              // 0..127
    int lk = (tid & 1) * 16;          // 0 or 16
    const __half* xg = g_xh + (size_t)(m0 + lrow) * C_ + lk;
    const __half* wg = g_Wqkvh + (size_t)(n0 + lrow) * C_ + lk;

    uint32_t asb[2] = { (uint32_t)__cvta_generic_to_shared(As[0]),
                        (uint32_t)__cvta_generic_to_shared(As[1]) };
    uint32_t bsb[2] = { (uint32_t)__cvta_generic_to_shared(Bs[0]),
                        (uint32_t)__cvta_generic_to_shared(Bs[1]) };
    uint32_t sdst = (lrow * 40 + lk) * 2;
    uint32_t afrag = ((wm * 64 + (lane & 15)) * 40 + (lane >> 4) * 8) * 2;
    uint32_t bfrag = ((wn * 32 + (lane & 15)) * 40 + (lane >> 4) * 8) * 2;

    float c[16][4];
#pragma unroll
    for (int f = 0; f < 16; ++f)
#pragma unroll
        for (int i = 0; i < 4; ++i) c[f][i] = 0.0f;

    // prologue
    cp16(asb[0] + sdst, xg);      cp16(asb[0] + sdst + 16, xg + 8);
    cp16(bsb[0] + sdst, wg);      cp16(bsb[0] + sdst + 16, wg + 8);
    CP_COMMIT();
    CP_WAIT0();
    __syncthreads();

    for (int it = 0; it < 16; ++it) {
        int buf = it & 1;
        if (it < 15) {
            int k0 = (it + 1) * 32;
            cp16(asb[buf ^ 1] + sdst, xg + k0);      cp16(asb[buf ^ 1] + sdst + 16, xg + k0 + 8);
            cp16(bsb[buf ^ 1] + sdst, wg + k0);      cp16(bsb[buf ^ 1] + sdst + 16, wg + k0 + 8);
            CP_COMMIT();
        }
#pragma unroll
        for (int ks = 0; ks < 2; ++ks) {
            uint32_t a[4][4];
#pragma unroll
            for (int mf = 0; mf < 4; ++mf)
                ldsm4(a[mf][0], a[mf][1], a[mf][2], a[mf][3],
                      asb[buf] + afrag + (mf * 16 * 40 + ks * 16) * 2);
#pragma unroll
            for (int p = 0; p < 2; ++p) {
                uint32_t b0, b1, b2, b3;
                ldsm4(b0, b1, b2, b3, bsb[buf] + bfrag + (p * 16 * 40 + ks * 16) * 2);
#pragma unroll
                for (int mf = 0; mf < 4; ++mf) {
                    mma16(c[mf * 4 + 2 * p],     a[mf][0], a[mf][1], a[mf][2], a[mf][3], b0, b2);
                    mma16(c[mf * 4 + 2 * p + 1], a[mf][0], a[mf][1], a[mf][2], a[mf][3], b1, b3);
                }
            }
        }
        if (it < 15) {
            CP_WAIT0();
            __syncthreads();
        }
    }

    // RoPE epilogue + scatter (fp32 math, fp16 store)
#pragma unroll
    for (int mf = 0; mf < 4; ++mf) {
#pragma unroll
        for (int half = 0; half < 2; ++half) {
            int m = m0 + wm * 64 + mf * 16 + lq + half * 8;   // global row
            int b = m >> 11;
            int n = m & 2047;
#pragma unroll
            for (int nf = 0; nf < 4; ++nf) {
                int col = n0 + wn * 32 + nf * 8 + 2 * lr;
                int s = col >> 9;
                int h = (col >> 6) & 7;
                int d = col & 63;
                float v0 = c[mf * 4 + nf][half * 2 + 0];
                float v1 = c[mf * 4 + nf][half * 2 + 1];
                if (s == 2) {
                    size_t vb = ((size_t)((b * 8 + h) * 64 + d)) * 2048 + n;
                    g_Vth[vb] = __float2half(v0);
                    g_Vth[vb + 2048] = __float2half(v1);
                } else {
                    size_t base = ((size_t)((b * 8 + h) * 2048 + n)) * 64 + d;
                    int i2 = d >> 1;
                    float ct = g_cos[m * 32 + i2];
                    float st = g_sin[m * 32 + i2];
                    __half2 hv = __floats2half2_rn(v0 * ct - v1 * st, v0 * st + v1 * ct);
                    if (s == 0) *(__half2*)&g_Qh[base] = hv;
                    else        *(__half2*)&g_Kh[base] = hv;
                }
            }
        }
    }
}

// ---------------------------------------------------------------------------
// Kernel 2: flash attention, fp16 mma, register-resident P, 2-stage K/V pipe.
//   Q tile 128 x 64, KV tile 64, 8 warps (16 q-rows each).
//   grid (16 q-tiles, 32 b*h), 256 threads, static smem ~37 KB -> 2 CTA/SM.
// ---------------------------------------------------------------------------
__global__ __launch_bounds__(256, 2) void attn_h(const float* __restrict__ mask) {
    __shared__ __half Ks[2][64 * 72];
    __shared__ __half Vs[2][64 * 72];
    __shared__ float Ms[2][64];

    int tid = threadIdx.x;
    int w = tid >> 5, lane = tid & 31;
    int lq = lane >> 2, lr = lane & 3;
    int bh = blockIdx.y;
    int b = bh >> 3, h = bh & 7;
    int q0 = blockIdx.x * 128;

    const __half* Qg = g_Qh + ((size_t)bh * 2048 + q0) * 64;
    const __half* Kg = g_Kh + (size_t)bh * 2048 * 64;
    const __half* Vg = g_Vth + (size_t)bh * 64 * 2048;
    const float* maskb = mask + b * 2048;

    // Q fragments held in registers for the whole kernel
    uint32_t qf[4][4];
    int qrow = w * 16 + lq;
#pragma unroll
    for (int ks = 0; ks < 4; ++ks) {
        qf[ks][0] = *(const uint32_t*)(Qg + (size_t)qrow * 64 + ks * 16 + 2 * lr);
        qf[ks][1] = *(const uint32_t*)(Qg + (size_t)(qrow + 8) * 64 + ks * 16 + 2 * lr);
        qf[ks][2] = *(const uint32_t*)(Qg + (size_t)qrow * 64 + ks * 16 + 8 + 2 * lr);
        qf[ks][3] = *(const uint32_t*)(Qg + (size_t)(qrow + 8) * 64 + ks * 16 + 8 + 2 * lr);
    }

    uint32_t ksb[2] = { (uint32_t)__cvta_generic_to_shared(Ks[0]),
                        (uint32_t)__cvta_generic_to_shared(Ks[1]) };
    uint32_t vsb[2] = { (uint32_t)__cvta_generic_to_shared(Vs[0]),
                        (uint32_t)__cvta_generic_to_shared(Vs[1]) };
    uint32_t bfrag = ((lane & 15) * 72 + (lane >> 4) * 8) * 2;

    // cp.async chunk mapping: 512 16B-chunks per tile, 2 per thread
    int r0c = tid >> 3,         c0c = (tid & 7) * 8;
    int r1c = (tid + 256) >> 3, c1c = ((tid + 256) & 7) * 8;

    float co[8][4];
#pragma unroll
    for (int nf = 0; nf < 8; ++nf)
#pragma unroll
        for (int i = 0; i < 4; ++i) co[nf][i] = 0.0f;
    float mi0 = -INFINITY, mi1 = -INFINITY, li0 = 0.0f, li1 = 0.0f;

    // prologue: load tile 0
    {
        cp16(ksb[0] + (r0c * 72 + c0c) * 2, Kg + (size_t)r0c * 64 + c0c);
        cp16(ksb[0] + (r1c * 72 + c1c) * 2, Kg + (size_t)r1c * 64 + c1c);
        cp16(vsb[0] + (r0c * 72 + c0c) * 2, Vg + (size_t)r0c * 2048 + c0c);
        cp16(vsb[0] + (r1c * 72 + c1c) * 2, Vg + (size_t)r1c * 2048 + c1c);
        CP_COMMIT();
        if (tid < 64) Ms[0][tid] = maskb[tid];
        CP_WAIT0();
        __syncthreads();
    }

    for (int kt = 0; kt < 32; ++kt) {
        int buf = kt & 1;
        if (kt < 31) {
            int nk = kt + 1;
            cp16(ksb[buf ^ 1] + (r0c * 72 + c0c) * 2, Kg + (size_t)(nk * 64 + r0c) * 64 + c0c);
            cp16(ksb[buf ^ 1] + (r1c * 72 + c1c) * 2, Kg + (size_t)(nk * 64 + r1c) * 64 + c1c);
            cp16(vsb[buf ^ 1] + (r0c * 72 + c0c) * 2, Vg + (size_t)r0c * 2048 + nk * 64 + c0c);
            cp16(vsb[buf ^ 1] + (r1c * 72 + c1c) * 2, Vg + (size_t)r1c * 2048 + nk * 64 + c1c);
            CP_COMMIT();
            if (tid < 64) Ms[buf ^ 1][tid] = maskb[nk * 64 + tid];
        }

        // S = Q K^T
        float cs[8][4];
#pragma unroll
        for (int nf = 0; nf < 8; ++nf)
#pragma unroll
            for (int i = 0; i < 4; ++i) cs[nf][i] = 0.0f;

#pragma unroll
        for (int ks = 0; ks < 4; ++ks) {
#pragma unroll
            for (int p = 0; p < 4; ++p) {
                uint32_t b0, b1, b2, b3;
                ldsm4(b0, b1, b2, b3, ksb[buf] + bfrag + (p * 16 * 72 + ks * 16) * 2);
                mma16(cs[2 * p],     qf[ks][0], qf[ks][1], qf[ks][2], qf[ks][3], b0, b2);
                mma16(cs[2 * p + 1], qf[ks][0], qf[ks][1], qf[ks][2], qf[ks][3], b1, b3);
            }
        }

        // scale + mask + online softmax (fp32)
        float rm0 = -INFINITY, rm1 = -INFINITY;
#pragma unroll
        for (int nf = 0; nf < 8; ++nf) {
            float mk0 = Ms[buf][nf * 8 + 2 * lr];
            float mk1 = Ms[buf][nf * 8 + 2 * lr + 1];
            cs[nf][0] = cs[nf][0] * 0.125f + mk0;
            cs[nf][1] = cs[nf][1] * 0.125f + mk1;
            cs[nf][2] = cs[nf][2] * 0.125f + mk0;
            cs[nf][3] = cs[nf][3] * 0.125f + mk1;
            rm0 = fmaxf(rm0, fmaxf(cs[nf][0], cs[nf][1]));
            rm1 = fmaxf(rm1, fmaxf(cs[nf][2], cs[nf][3]));
        }
        rm0 = fmaxf(rm0, __shfl_xor_sync(0xffffffffu, rm0, 1));
        rm0 = fmaxf(rm0, __shfl_xor_sync(0xffffffffu, rm0, 2));
        rm1 = fmaxf(rm1, __shfl_xor_sync(0xffffffffu, rm1, 1));
        rm1 = fmaxf(rm1, __shfl_xor_sync(0xffffffffu, rm1, 2));

        float mn0 = fmaxf(mi0, rm0);
        float mn1 = fmaxf(mi1, rm1);
        float corr0 = __expf(mi0 - mn0);
        float corr1 = __expf(mi1 - mn1);
        float sum0 = 0.0f, sum1 = 0.0f;
#pragma unroll
        for (int nf = 0; nf < 8; ++nf) {
            cs[nf][0] = __expf(cs[nf][0] - mn0);
            cs[nf][1] = __expf(cs[nf][1] - mn0);
            cs[nf][2] = __expf(cs[nf][2] - mn1);
            cs[nf][3] = __expf(cs[nf][3] - mn1);
            sum0 += cs[nf][0] + cs[nf][1];
            sum1 += cs[nf][2] + cs[nf][3];
        }
        sum0 += __shfl_xor_sync(0xffffffffu, sum0, 1);
        sum0 += __shfl_xor_sync(0xffffffffu, sum0, 2);
        sum1 += __shfl_xor_sync(0xffffffffu, sum1, 1);
        sum1 += __shfl_xor_sync(0xffffffffu, sum1, 2);
        li0 = li0 * corr0 + sum0;
        li1 = li1 * corr1 + sum1;
        mi0 = mn0; mi1 = mn1;
#pragma unroll
        for (int nf = 0; nf < 8; ++nf) {
            co[nf][0] *= corr0; co[nf][1] *= corr0;
            co[nf][2] *= corr1; co[nf][3] *= corr1;
        }

        // O += P V — P packed in registers (C-layout == A-layout trick)
#pragma unroll
        for (int kc = 0; kc < 4; ++kc) {
            uint32_t pa0 = pack2(cs[2 * kc][0],     cs[2 * kc][1]);
            uint32_t pa1 = pack2(cs[2 * kc][2],     cs[2 * kc][3]);
            uint32_t pa2 = pack2(cs[2 * kc + 1][0], cs[2 * kc + 1][1]);
            uint32_t pa3 = pack2(cs[2 * kc + 1][2], cs[2 * kc + 1][3]);
#pragma unroll
            for (int p = 0; p < 4; ++p) {
                uint32_t b0, b1, b2, b3;
                ldsm4(b0, b1, b2, b3, vsb[buf] + bfrag + (p * 16 * 72 + kc * 16) * 2);
                mma16(co[2 * p],     pa0, pa1, pa2, pa3, b0, b2);
                mma16(co[2 * p + 1], pa0, pa1, pa2, pa3, b1, b3);
            }
        }

        if (kt < 31) {
            CP_WAIT0();
            __syncthreads();
        }
    }

    // normalize + write g_Oh [B,N,C] (half)
    float inv0 = 1.0f / li0;
    float inv1 = 1.0f / li1;
    int m0g = q0 + w * 16 + lq;
    int m1g = m0g + 8;
#pragma unroll
    for (int nf = 0; nf < 8; ++nf) {
        int col = h * 64 + nf * 8 + 2 * lr;
        *(__half2*)&g_Oh[((size_t)(b * 2048 + m0g)) * 512 + col] =
            __floats2half2_rn(co[nf][0] * inv0, co[nf][1] * inv0);
        *(__half2*)&g_Oh[((size_t)(b * 2048 + m1g)) * 512 + col] =
            __floats2half2_rn(co[nf][2] * inv1, co[nf][3] * inv1);
    }
}

// ---------------------------------------------------------------------------
// Kernel 3: output projection fp16 mma (M=8192, N=512, K=512) + bias, fp32 out
// ---------------------------------------------------------------------------
__global__ __launch_bounds__(256) void gemm_proj_h(const float* __restrict__ bias,
                                                   float* __restrict__ out) {
    __shared__ __half As[2][128 * 40];
    __shared__ __half Bs[2][128 * 40];

    int tid = threadIdx.x;
    int w = tid >> 5, lane = tid & 31;
    int lq = lane >> 2, lr = lane & 3;
    int wm = w & 1, wn = w >> 1;
    int m0 = blockIdx.y * 128;
    int n0 = blockIdx.x * 128;

    int lrow = tid >> 1;
    int lk = (tid & 1) * 16;
    const __half* ag = g_Oh + (size_t)(m0 + lrow) * C_ + lk;
    const __half* wg = g_Wprojh + (size_t)(n0 + lrow) * C_ + lk;

    uint32_t asb[2] = { (uint32_t)__cvta_generic_to_shared(As[0]),
                        (uint32_t)__cvta_generic_to_shared(As[1]) };
    uint32_t bsb[2] = { (uint32_t)__cvta_generic_to_shared(Bs[0]),
                        (uint32_t)__cvta_generic_to_shared(Bs[1]) };
    uint32_t sdst = (lrow * 40 + lk) * 2;
    uint32_t afrag = ((wm * 64 + (lane & 15)) * 40 + (lane >> 4) * 8) * 2;
    uint32_t bfrag = ((wn * 32 + (lane & 15)) * 40 + (lane >> 4) * 8) * 2;

    float c[16][4];
#pragma unroll
    for (int f = 0; f < 16; ++f)
#pragma unroll
        for (int i = 0; i < 4; ++i) c[f][i] = 0.0f;

    cp16(asb[0] + sdst, ag);      cp16(asb[0] + sdst + 16, ag + 8);
    cp16(bsb[0] + sdst, wg);      cp16(bsb[0] + sdst + 16, wg + 8);
    CP_COMMIT();
    CP_WAIT0();
    __syncthreads();

    for (int it = 0; it < 16; ++it) {
        int buf = it & 1;
        if (it < 15) {
            int k0 = (it + 1) * 32;
            cp16(asb[buf ^ 1] + sdst, ag + k0);      cp16(asb[buf ^ 1] + sdst + 16, ag + k0 + 8);
            cp16(bsb[buf ^ 1] + sdst, wg + k0);      cp16(bsb[buf ^ 1] + sdst + 16, wg + k0 + 8);
            CP_COMMIT();
        }
#pragma unroll
        for (int ks = 0; ks < 2; ++ks) {
            uint32_t a[4][4];
#pragma unroll
            for (int mf = 0; mf < 4; ++mf)
                ldsm4(a[mf][0], a[mf][1], a[mf][2], a[mf][3],
                      asb[buf] + afrag + (mf * 16 * 40 + ks * 16) * 2);
#pragma unroll
            for (int p = 0; p < 2; ++p) {
                uint32_t b0, b1, b2, b3;
                ldsm4(b0, b1, b2, b3, bsb[buf] + bfrag + (p * 16 * 40 + ks * 16) * 2);
#pragma unroll
                for (int mf = 0; mf < 4; ++mf) {
                    mma16(c[mf * 4 + 2 * p],     a[mf][0], a[mf][1], a[mf][2], a[mf][3], b0, b2);
                    mma16(c[mf * 4 + 2 * p + 1], a[mf][0], a[mf][1], a[mf][2], a[mf][3], b1, b3);
                }
            }
        }
        if (it < 15) {
            CP_WAIT0();
            __syncthreads();
        }
    }

#pragma unroll
    for (int mf = 0; mf < 4; ++mf) {
#pragma unroll
        for (int half = 0; half < 2; ++half) {
            int m = m0 + wm * 64 + mf * 16 + lq + half * 8;
#pragma unroll
            for (int nf = 0; nf < 4; ++nf) {
                int col = n0 + wn * 32 + nf * 8 + 2 * lr;
                float v0 = c[mf * 4 + nf][half * 2 + 0] + bias[col];
                float v1 = c[mf * 4 + nf][half * 2 + 1] + bias[col + 1];
                *(float2*)&out[(size_t)m * 512 + col] = make_float2(v0, v1);
            }
        }
    }
}

// ---------------------------------------------------------------------------
extern "C" void kernel_launch(void* const* d_in, const int* in_sizes, int n_in,
                              void* d_out, int out_size) {
    const float* x     = (const float*)d_in[0];
    const float* mask  = (const float*)d_in[1];
    const float* times = (const float*)d_in[2];
    const float* Wqkv  = (const float*)d_in[3];
    const float* Wproj = (const float*)d_in[4];
    const float* bproj = (const float*)d_in[5];
    (void)in_sizes; (void)n_in; (void)out_size;   // num_cls_token == 0 (fixed input)

    // resolve device-global addresses for conversion targets
    __half* xh;     cudaGetSymbolAddress((void**)&xh, g_xh);
    __half* wqkvh;  cudaGetSymbolAddress((void**)&wqkvh, g_Wqkvh);
    __half* wprojh; cudaGetSymbolAddress((void**)&wprojh, g_Wprojh);

    f2h_kernel<<<(M_ * C_ / 4 + 255) / 256, 256>>>(x, xh, M_ * C_ / 4);
    f2h_kernel<<<(NQKV * C_ / 4 + 255) / 256, 256>>>(Wqkv, wqkvh, NQKV * C_ / 4);
    f2h_kernel<<<(C_ * C_ / 4 + 255) / 256, 256>>>(Wproj, wprojh, C_ * C_ / 4);
    rope_table_kernel<<<(B_ * N_ * 32 + 255) / 256, 256>>>(times);

    gemm_qkv_h<<<dim3(NQKV / 128, M_ / 128), 256>>>();
    attn_h<<<dim3(N_ / 128, B_ * H_), 256>>>(mask);
    gemm_proj_h<<<dim3(C_ / 128, M_ / 128), 256>>>(bproj, (float*)d_out);
}

// round 8
// speedup vs baseline: 5.6033x; 1.0697x over previous
#include <cuda_runtime.h>
#include <cuda_fp16.h>
#include <math.h>
#include <stdint.h>

// Problem constants
#define B_ 4
#define N_ 2048
#define C_ 512
#define H_ 8
#define DH 64
#define M_ (B_ * N_)          // 8192
#define NQKV (3 * C_)         // 1536

#define SC_LOG2E 0.18033688011112042f   // 0.125 * log2(e)
#define LOG2E    1.4426950408889634f

// Scratch (device globals; no allocation allowed)
__device__ __half g_xh[M_ * C_];
__device__ __half g_Wqkvh[NQKV * C_];
__device__ __half g_Wprojh[C_ * C_];
__device__ __half g_Qh[B_ * H_ * N_ * DH];    // pre-scaled by SC_LOG2E
__device__ __half g_Kh[B_ * H_ * N_ * DH];
__device__ __half g_Vth[B_ * H_ * DH * N_];   // V transposed: [b,h,d,n]
__device__ __half g_Oh[M_ * C_];
__device__ float g_cos[B_ * N_ * (DH / 2)];
__device__ float g_sin[B_ * N_ * (DH / 2)];

// ---------------------------------------------------------------------------
// helpers
// ---------------------------------------------------------------------------
__device__ __forceinline__ void mma16(float* c,
                                      uint32_t a0, uint32_t a1, uint32_t a2, uint32_t a3,
                                      uint32_t b0, uint32_t b1) {
    asm volatile(
        "mma.sync.aligned.m16n8k16.row.col.f32.f16.f16.f32 "
        "{%0,%1,%2,%3},{%4,%5,%6,%7},{%8,%9},{%0,%1,%2,%3};"
        : "+f"(c[0]), "+f"(c[1]), "+f"(c[2]), "+f"(c[3])
        : "r"(a0), "r"(a1), "r"(a2), "r"(a3), "r"(b0), "r"(b1));
}

__device__ __forceinline__ void ldsm4(uint32_t& r0, uint32_t& r1, uint32_t& r2, uint32_t& r3,
                                      uint32_t addr) {
    asm volatile("ldmatrix.sync.aligned.m8n8.x4.shared.b16 {%0,%1,%2,%3}, [%4];"
                 : "=r"(r0), "=r"(r1), "=r"(r2), "=r"(r3) : "r"(addr));
}

__device__ __forceinline__ void cp16(uint32_t dst, const void* src) {
    asm volatile("cp.async.cg.shared.global [%0], [%1], 16;" :: "r"(dst), "l"(src));
}
#define CP_COMMIT() asm volatile("cp.async.commit_group;")
#define CP_WAIT0()  asm volatile("cp.async.wait_group 0;")

__device__ __forceinline__ uint32_t pack2(float lo, float hi) {
    __half2 t = __floats2half2_rn(lo, hi);
    return *reinterpret_cast<uint32_t*>(&t);
}

__device__ __forceinline__ float ex2f(float x) {
    float y;
    asm("ex2.approx.ftz.f32 %0, %1;" : "=f"(y) : "f"(x));
    return y;
}

// ---------------------------------------------------------------------------
// Kernel: fp32 -> fp16 conversion for x, Wqkv, Wproj in one launch.
// segment boundaries in float4 units.
// ---------------------------------------------------------------------------
#define X_N4    (M_ * C_ / 4)            // 1048576
#define WQKV_N4 (NQKV * C_ / 4)          // 196608
#define WPROJ_N4 (C_ * C_ / 4)           // 65536
#define F2H_TOTAL (X_N4 + WQKV_N4 + WPROJ_N4)

__global__ void f2h_all_kernel(const float* __restrict__ x,
                               const float* __restrict__ wqkv,
                               const float* __restrict__ wproj) {
    int i = blockIdx.x * 256 + threadIdx.x;
    if (i >= F2H_TOTAL) return;
    const float* src;
    __half* dst;
    int off;
    if (i < X_N4) { src = x; dst = g_xh; off = i; }
    else if (i < X_N4 + WQKV_N4) { src = wqkv; dst = g_Wqkvh; off = i - X_N4; }
    else { src = wproj; dst = g_Wprojh; off = i - X_N4 - WQKV_N4; }
    float4 v = ((const float4*)src)[off];
    __half2* o = (__half2*)dst;
    o[2 * off]     = __floats2half2_rn(v.x, v.y);
    o[2 * off + 1] = __floats2half2_rn(v.z, v.w);
}

// ---------------------------------------------------------------------------
// Kernel 0: RoPE cos/sin tables.
// ---------------------------------------------------------------------------
__global__ void rope_table_kernel(const float* __restrict__ times) {
    int idx = blockIdx.x * 256 + threadIdx.x;
    if (idx >= B_ * N_ * 32) return;
    int i = idx & 31;
    int bn = idx >> 5;
    float pos = rintf(times[bn] * 30.0f);
    float inv_freq = powf(10000.0f, -(float)i / 32.0f);
    float f = pos * inv_freq;
    float s, c;
    sincosf(f, &s, &c);
    g_cos[idx] = c;
    g_sin[idx] = s;
}

// ---------------------------------------------------------------------------
// Kernel 1: QKV GEMM fp16 mma (M=8192, N=1536, K=512) + RoPE + scatter
//   128x128 tile, BK=32, 8 warps as 2(m) x 4(n), double-buffered cp.async.
//   Q is written pre-scaled by SC_LOG2E (attention softmax in exp2 domain).
// ---------------------------------------------------------------------------
__global__ __launch_bounds__(256) void gemm_qkv_h() {
    __shared__ __half As[2][128 * 40];
    __shared__ __half Bs[2][128 * 40];

    int tid = threadIdx.x;
    int w = tid >> 5, lane = tid & 31;
    int lq = lane >> 2, lr = lane & 3;
    int wm = w & 1, wn = w >> 1;
    int m0 = blockIdx.y * 128;
    int n0 = blockIdx.x * 128;

    int lrow = tid >> 1;              // 0..127
    int lk = (tid & 1) * 16;          // 0 or 16
    const __half* xg = g_xh + (size_t)(m0 + lrow) * C_ + lk;
    const __half* wg = g_Wqkvh + (size_t)(n0 + lrow) * C_ + lk;

    uint32_t asb[2] = { (uint32_t)__cvta_generic_to_shared(As[0]),
                        (uint32_t)__cvta_generic_to_shared(As[1]) };
    uint32_t bsb[2] = { (uint32_t)__cvta_generic_to_shared(Bs[0]),
                        (uint32_t)__cvta_generic_to_shared(Bs[1]) };
    uint32_t sdst = (lrow * 40 + lk) * 2;
    uint32_t afrag = ((wm * 64 + (lane & 15)) * 40 + (lane >> 4) * 8) * 2;
    uint32_t bfrag = ((wn * 32 + (lane & 15)) * 40 + (lane >> 4) * 8) * 2;

    float c[16][4];
#pragma unroll
    for (int f = 0; f < 16; ++f)
#pragma unroll
        for (int i = 0; i < 4; ++i) c[f][i] = 0.0f;

    // prologue
    cp16(asb[0] + sdst, xg);      cp16(asb[0] + sdst + 16, xg + 8);
    cp16(bsb[0] + sdst, wg);      cp16(bsb[0] + sdst + 16, wg + 8);
    CP_COMMIT();
    CP_WAIT0();
    __syncthreads();

    for (int it = 0; it < 16; ++it) {
        int buf = it & 1;
        if (it < 15) {
            int k0 = (it + 1) * 32;
            cp16(asb[buf ^ 1] + sdst, xg + k0);      cp16(asb[buf ^ 1] + sdst + 16, xg + k0 + 8);
            cp16(bsb[buf ^ 1] + sdst, wg + k0);      cp16(bsb[buf ^ 1] + sdst + 16, wg + k0 + 8);
            CP_COMMIT();
        }
#pragma unroll
        for (int ks = 0; ks < 2; ++ks) {
            uint32_t a[4][4];
#pragma unroll
            for (int mf = 0; mf < 4; ++mf)
                ldsm4(a[mf][0], a[mf][1], a[mf][2], a[mf][3],
                      asb[buf] + afrag + (mf * 16 * 40 + ks * 16) * 2);
#pragma unroll
            for (int p = 0; p < 2; ++p) {
                uint32_t b0, b1, b2, b3;
                ldsm4(b0, b1, b2, b3, bsb[buf] + bfrag + (p * 16 * 40 + ks * 16) * 2);
#pragma unroll
                for (int mf = 0; mf < 4; ++mf) {
                    mma16(c[mf * 4 + 2 * p],     a[mf][0], a[mf][1], a[mf][2], a[mf][3], b0, b2);
                    mma16(c[mf * 4 + 2 * p + 1], a[mf][0], a[mf][1], a[mf][2], a[mf][3], b1, b3);
                }
            }
        }
        if (it < 15) {
            CP_WAIT0();
            __syncthreads();
        }
    }

    // RoPE epilogue + scatter (fp32 math, fp16 store). Q pre-scaled by SC_LOG2E.
#pragma unroll
    for (int mf = 0; mf < 4; ++mf) {
#pragma unroll
        for (int half = 0; half < 2; ++half) {
            int m = m0 + wm * 64 + mf * 16 + lq + half * 8;   // global row
            int b = m >> 11;
            int n = m & 2047;
#pragma unroll
            for (int nf = 0; nf < 4; ++nf) {
                int col = n0 + wn * 32 + nf * 8 + 2 * lr;
                int s = col >> 9;
                int h = (col >> 6) & 7;
                int d = col & 63;
                float v0 = c[mf * 4 + nf][half * 2 + 0];
                float v1 = c[mf * 4 + nf][half * 2 + 1];
                if (s == 2) {
                    size_t vb = ((size_t)((b * 8 + h) * 64 + d)) * 2048 + n;
                    g_Vth[vb] = __float2half(v0);
                    g_Vth[vb + 2048] = __float2half(v1);
                } else {
                    size_t base = ((size_t)((b * 8 + h) * 2048 + n)) * 64 + d;
                    int i2 = d >> 1;
                    float sc = (s == 0) ? SC_LOG2E : 1.0f;
                    float ct = g_cos[m * 32 + i2] * sc;
                    float st = g_sin[m * 32 + i2] * sc;
                    __half2 hv = __floats2half2_rn(v0 * ct - v1 * st, v0 * st + v1 * ct);
                    if (s == 0) *(__half2*)&g_Qh[base] = hv;
                    else        *(__half2*)&g_Kh[base] = hv;
                }
            }
        }
    }
}

// ---------------------------------------------------------------------------
// Kernel 2: flash attention, fp16 mma, register-resident P, 2-stage K/V pipe.
//   Softmax in exp2 domain (Q pre-scaled, mask pre-multiplied by log2e).
//   Q tile 128 x 64, KV tile 64, 8 warps (16 q-rows each).
// ---------------------------------------------------------------------------
__global__ __launch_bounds__(256, 2) void attn_h(const float* __restrict__ mask) {
    __shared__ __half Ks[2][64 * 72];
    __shared__ __half Vs[2][64 * 72];
    __shared__ float Ms[2][64];

    int tid = threadIdx.x;
    int w = tid >> 5, lane = tid & 31;
    int lq = lane >> 2, lr = lane & 3;
    int bh = blockIdx.y;
    int b = bh >> 3, h = bh & 7;
    int q0 = blockIdx.x * 128;

    const __half* Qg = g_Qh + ((size_t)bh * 2048 + q0) * 64;
    const __half* Kg = g_Kh + (size_t)bh * 2048 * 64;
    const __half* Vg = g_Vth + (size_t)bh * 64 * 2048;
    const float* maskb = mask + b * 2048;

    // Q fragments held in registers for the whole kernel
    uint32_t qf[4][4];
    int qrow = w * 16 + lq;
#pragma unroll
    for (int ks = 0; ks < 4; ++ks) {
        qf[ks][0] = *(const uint32_t*)(Qg + (size_t)qrow * 64 + ks * 16 + 2 * lr);
        qf[ks][1] = *(const uint32_t*)(Qg + (size_t)(qrow + 8) * 64 + ks * 16 + 2 * lr);
        qf[ks][2] = *(const uint32_t*)(Qg + (size_t)qrow * 64 + ks * 16 + 8 + 2 * lr);
        qf[ks][3] = *(const uint32_t*)(Qg + (size_t)(qrow + 8) * 64 + ks * 16 + 8 + 2 * lr);
    }

    uint32_t ksb[2] = { (uint32_t)__cvta_generic_to_shared(Ks[0]),
                        (uint32_t)__cvta_generic_to_shared(Ks[1]) };
    uint32_t vsb[2] = { (uint32_t)__cvta_generic_to_shared(Vs[0]),
                        (uint32_t)__cvta_generic_to_shared(Vs[1]) };
    uint32_t bfrag = ((lane & 15) * 72 + (lane >> 4) * 8) * 2;

    // cp.async chunk mapping: 512 16B-chunks per tile, 2 per thread
    int r0c = tid >> 3,         c0c = (tid & 7) * 8;
    int r1c = (tid + 256) >> 3, c1c = ((tid + 256) & 7) * 8;

    float co[8][4];
#pragma unroll
    for (int nf = 0; nf < 8; ++nf)
#pragma unroll
        for (int i = 0; i < 4; ++i) co[nf][i] = 0.0f;
    float mi0 = -INFINITY, mi1 = -INFINITY, li0 = 0.0f, li1 = 0.0f;

    // prologue: load tile 0
    {
        cp16(ksb[0] + (r0c * 72 + c0c) * 2, Kg + (size_t)r0c * 64 + c0c);
        cp16(ksb[0] + (r1c * 72 + c1c) * 2, Kg + (size_t)r1c * 64 + c1c);
        cp16(vsb[0] + (r0c * 72 + c0c) * 2, Vg + (size_t)r0c * 2048 + c0c);
        cp16(vsb[0] + (r1c * 72 + c1c) * 2, Vg + (size_t)r1c * 2048 + c1c);
        CP_COMMIT();
        if (tid < 64) Ms[0][tid] = maskb[tid] * LOG2E;
        CP_WAIT0();
        __syncthreads();
    }

    for (int kt = 0; kt < 32; ++kt) {
        int buf = kt & 1;
        if (kt < 31) {
            int nk = kt + 1;
            cp16(ksb[buf ^ 1] + (r0c * 72 + c0c) * 2, Kg + (size_t)(nk * 64 + r0c) * 64 + c0c);
            cp16(ksb[buf ^ 1] + (r1c * 72 + c1c) * 2, Kg + (size_t)(nk * 64 + r1c) * 64 + c1c);
            cp16(vsb[buf ^ 1] + (r0c * 72 + c0c) * 2, Vg + (size_t)r0c * 2048 + nk * 64 + c0c);
            cp16(vsb[buf ^ 1] + (r1c * 72 + c1c) * 2, Vg + (size_t)r1c * 2048 + nk * 64 + c1c);
            CP_COMMIT();
            if (tid < 64) Ms[buf ^ 1][tid] = maskb[nk * 64 + tid] * LOG2E;
        }

        // S = Q K^T (already in log2 domain thanks to Q pre-scale)
        float cs[8][4];
#pragma unroll
        for (int nf = 0; nf < 8; ++nf)
#pragma unroll
            for (int i = 0; i < 4; ++i) cs[nf][i] = 0.0f;

#pragma unroll
        for (int ks = 0; ks < 4; ++ks) {
#pragma unroll
            for (int p = 0; p < 4; ++p) {
                uint32_t b0, b1, b2, b3;
                ldsm4(b0, b1, b2, b3, ksb[buf] + bfrag + (p * 16 * 72 + ks * 16) * 2);
                mma16(cs[2 * p],     qf[ks][0], qf[ks][1], qf[ks][2], qf[ks][3], b0, b2);
                mma16(cs[2 * p + 1], qf[ks][0], qf[ks][1], qf[ks][2], qf[ks][3], b1, b3);
            }
        }

        // mask add + online softmax (exp2 domain, fp32)
        float rm0 = -INFINITY, rm1 = -INFINITY;
#pragma unroll
        for (int nf = 0; nf < 8; ++nf) {
            float mk0 = Ms[buf][nf * 8 + 2 * lr];
            float mk1 = Ms[buf][nf * 8 + 2 * lr + 1];
            cs[nf][0] += mk0;
            cs[nf][1] += mk1;
            cs[nf][2] += mk0;
            cs[nf][3] += mk1;
            rm0 = fmaxf(rm0, fmaxf(cs[nf][0], cs[nf][1]));
            rm1 = fmaxf(rm1, fmaxf(cs[nf][2], cs[nf][3]));
        }
        rm0 = fmaxf(rm0, __shfl_xor_sync(0xffffffffu, rm0, 1));
        rm0 = fmaxf(rm0, __shfl_xor_sync(0xffffffffu, rm0, 2));
        rm1 = fmaxf(rm1, __shfl_xor_sync(0xffffffffu, rm1, 1));
        rm1 = fmaxf(rm1, __shfl_xor_sync(0xffffffffu, rm1, 2));

        float mn0 = fmaxf(mi0, rm0);
        float mn1 = fmaxf(mi1, rm1);
        float corr0 = ex2f(mi0 - mn0);
        float corr1 = ex2f(mi1 - mn1);
        float sum0 = 0.0f, sum1 = 0.0f;
#pragma unroll
        for (int nf = 0; nf < 8; ++nf) {
            cs[nf][0] = ex2f(cs[nf][0] - mn0);
            cs[nf][1] = ex2f(cs[nf][1] - mn0);
            cs[nf][2] = ex2f(cs[nf][2] - mn1);
            cs[nf][3] = ex2f(cs[nf][3] - mn1);
            sum0 += cs[nf][0] + cs[nf][1];
            sum1 += cs[nf][2] + cs[nf][3];
        }
        sum0 += __shfl_xor_sync(0xffffffffu, sum0, 1);
        sum0 += __shfl_xor_sync(0xffffffffu, sum0, 2);
        sum1 += __shfl_xor_sync(0xffffffffu, sum1, 1);
        sum1 += __shfl_xor_sync(0xffffffffu, sum1, 2);
        li0 = li0 * corr0 + sum0;
        li1 = li1 * corr1 + sum1;
        mi0 = mn0; mi1 = mn1;
#pragma unroll
        for (int nf = 0; nf < 8; ++nf) {
            co[nf][0] *= corr0; co[nf][1] *= corr0;
            co[nf][2] *= corr1; co[nf][3] *= corr1;
        }

        // O += P V — P packed in registers (C-layout == A-layout trick)
#pragma unroll
        for (int kc = 0; kc < 4; ++kc) {
            uint32_t pa0 = pack2(cs[2 * kc][0],     cs[2 * kc][1]);
            uint32_t pa1 = pack2(cs[2 * kc][2],     cs[2 * kc][3]);
            uint32_t pa2 = pack2(cs[2 * kc + 1][0], cs[2 * kc + 1][1]);
            uint32_t pa3 = pack2(cs[2 * kc + 1][2], cs[2 * kc + 1][3]);
#pragma unroll
            for (int p = 0; p < 4; ++p) {
                uint32_t b0, b1, b2, b3;
                ldsm4(b0, b1, b2, b3, vsb[buf] + bfrag + (p * 16 * 72 + kc * 16) * 2);
                mma16(co[2 * p],     pa0, pa1, pa2, pa3, b0, b2);
                mma16(co[2 * p + 1], pa0, pa1, pa2, pa3, b1, b3);
            }
        }

        if (kt < 31) {
            CP_WAIT0();
            __syncthreads();
        }
    }

    // normalize + write g_Oh [B,N,C] (half)
    float inv0 = 1.0f / li0;
    float inv1 = 1.0f / li1;
    int m0g = q0 + w * 16 + lq;
    int m1g = m0g + 8;
#pragma unroll
    for (int nf = 0; nf < 8; ++nf) {
        int col = h * 64 + nf * 8 + 2 * lr;
        *(__half2*)&g_Oh[((size_t)(b * 2048 + m0g)) * 512 + col] =
            __floats2half2_rn(co[nf][0] * inv0, co[nf][1] * inv0);
        *(__half2*)&g_Oh[((size_t)(b * 2048 + m1g)) * 512 + col] =
            __floats2half2_rn(co[nf][2] * inv1, co[nf][3] * inv1);
    }
}

// ---------------------------------------------------------------------------
// Kernel 3: output projection fp16 mma (M=8192, N=512, K=512) + bias, fp32 out
// ---------------------------------------------------------------------------
__global__ __launch_bounds__(256) void gemm_proj_h(const float* __restrict__ bias,
                                                   float* __restrict__ out) {
    __shared__ __half As[2][128 * 40];
    __shared__ __half Bs[2][128 * 40];

    int tid = threadIdx.x;
    int w = tid >> 5, lane = tid & 31;
    int lq = lane >> 2, lr = lane & 3;
    int wm = w & 1, wn = w >> 1;
    int m0 = blockIdx.y * 128;
    int n0 = blockIdx.x * 128;

    int lrow = tid >> 1;
    int lk = (tid & 1) * 16;
    const __half* ag = g_Oh + (size_t)(m0 + lrow) * C_ + lk;
    const __half* wg = g_Wprojh + (size_t)(n0 + lrow) * C_ + lk;

    uint32_t asb[2] = { (uint32_t)__cvta_generic_to_shared(As[0]),
                        (uint32_t)__cvta_generic_to_shared(As[1]) };
    uint32_t bsb[2] = { (uint32_t)__cvta_generic_to_shared(Bs[0]),
                        (uint32_t)__cvta_generic_to_shared(Bs[1]) };
    uint32_t sdst = (lrow * 40 + lk) * 2;
    uint32_t afrag = ((wm * 64 + (lane & 15)) * 40 + (lane >> 4) * 8) * 2;
    uint32_t bfrag = ((wn * 32 + (lane & 15)) * 40 + (lane >> 4) * 8) * 2;

    float c[16][4];
#pragma unroll
    for (int f = 0; f < 16; ++f)
#pragma unroll
        for (int i = 0; i < 4; ++i) c[f][i] = 0.0f;

    cp16(asb[0] + sdst, ag);      cp16(asb[0] + sdst + 16, ag + 8);
    cp16(bsb[0] + sdst, wg);      cp16(bsb[0] + sdst + 16, wg + 8);
    CP_COMMIT();
    CP_WAIT0();
    __syncthreads();

    for (int it = 0; it < 16; ++it) {
        int buf = it & 1;
        if (it < 15) {
            int k0 = (it + 1) * 32;
            cp16(asb[buf ^ 1] + sdst, ag + k0);      cp16(asb[buf ^ 1] + sdst + 16, ag + k0 + 8);
            cp16(bsb[buf ^ 1] + sdst, wg + k0);      cp16(bsb[buf ^ 1] + sdst + 16, wg + k0 + 8);
            CP_COMMIT();
        }
#pragma unroll
        for (int ks = 0; ks < 2; ++ks) {
            uint32_t a[4][4];
#pragma unroll
            for (int mf = 0; mf < 4; ++mf)
                ldsm4(a[mf][0], a[mf][1], a[mf][2], a[mf][3],
                      asb[buf] + afrag + (mf * 16 * 40 + ks * 16) * 2);
#pragma unroll
            for (int p = 0; p < 2; ++p) {
                uint32_t b0, b1, b2, b3;
                ldsm4(b0, b1, b2, b3, bsb[buf] + bfrag + (p * 16 * 40 + ks * 16) * 2);
#pragma unroll
                for (int mf = 0; mf < 4; ++mf) {
                    mma16(c[mf * 4 + 2 * p],     a[mf][0], a[mf][1], a[mf][2], a[mf][3], b0, b2);
                    mma16(c[mf * 4 + 2 * p + 1], a[mf][0], a[mf][1], a[mf][2], a[mf][3], b1, b3);
                }
            }
        }
        if (it < 15) {
            CP_WAIT0();
            __syncthreads();
        }
    }

#pragma unroll
    for (int mf = 0; mf < 4; ++mf) {
#pragma unroll
        for (int half = 0; half < 2; ++half) {
            int m = m0 + wm * 64 + mf * 16 + lq + half * 8;
#pragma unroll
            for (int nf = 0; nf < 4; ++nf) {
                int col = n0 + wn * 32 + nf * 8 + 2 * lr;
                float v0 = c[mf * 4 + nf][half * 2 + 0] + bias[col];
                float v1 = c[mf * 4 + nf][half * 2 + 1] + bias[col + 1];
                *(float2*)&out[(size_t)m * 512 + col] = make_float2(v0, v1);
            }
        }
    }
}

// ---------------------------------------------------------------------------
extern "C" void kernel_launch(void* const* d_in, const int* in_sizes, int n_in,
                              void* d_out, int out_size) {
    const float* x     = (const float*)d_in[0];
    const float* mask  = (const float*)d_in[1];
    const float* times = (const float*)d_in[2];
    const float* Wqkv  = (const float*)d_in[3];
    const float* Wproj = (const float*)d_in[4];
    const float* bproj = (const float*)d_in[5];
    (void)in_sizes; (void)n_in; (void)out_size;   // num_cls_token == 0 (fixed input)

    f2h_all_kernel<<<(F2H_TOTAL + 255) / 256, 256>>>(x, Wqkv, Wproj);
    rope_table_kernel<<<(B_ * N_ * 32 + 255) / 256, 256>>>(times);

    gemm_qkv_h<<<dim3(NQKV / 128, M_ / 128), 256>>>();
    attn_h<<<dim3(N_ / 128, B_ * H_), 256>>>(mask);
    gemm_proj_h<<<dim3(C_ / 128, M_ / 128), 256>>>(bproj, (float*)d_out);
}

// round 9
// speedup vs baseline: 5.6463x; 1.0077x over previous
#include <cuda_runtime.h>
#include <cuda_fp16.h>
#include <math.h>
#include <stdint.h>

// Problem constants
#define B_ 4
#define N_ 2048
#define C_ 512
#define H_ 8
#define DH 64
#define M_ (B_ * N_)          // 8192
#define NQKV (3 * C_)         // 1536

#define SC_LOG2E 0.18033688011112042f   // 0.125 * log2(e)
#define LOG2E    1.4426950408889634f

// Scratch (device globals; no allocation allowed)
__device__ __half g_xh[M_ * C_];
__device__ __half g_Wqkvh[NQKV * C_];
__device__ __half g_Wprojh[C_ * C_];
__device__ __half g_Qh[B_ * H_ * N_ * DH];    // pre-scaled by SC_LOG2E
__device__ __half g_Kh[B_ * H_ * N_ * DH];
__device__ __half g_Vth[B_ * H_ * DH * N_];   // V transposed: [b,h,d,n]
__device__ __half g_Oh[M_ * C_];
__device__ float g_cos[B_ * N_ * (DH / 2)];
__device__ float g_sin[B_ * N_ * (DH / 2)];

// ---------------------------------------------------------------------------
// helpers
// ---------------------------------------------------------------------------
__device__ __forceinline__ void mma16(float* c,
                                      uint32_t a0, uint32_t a1, uint32_t a2, uint32_t a3,
                                      uint32_t b0, uint32_t b1) {
    asm volatile(
        "mma.sync.aligned.m16n8k16.row.col.f32.f16.f16.f32 "
        "{%0,%1,%2,%3},{%4,%5,%6,%7},{%8,%9},{%0,%1,%2,%3};"
        : "+f"(c[0]), "+f"(c[1]), "+f"(c[2]), "+f"(c[3])
        : "r"(a0), "r"(a1), "r"(a2), "r"(a3), "r"(b0), "r"(b1));
}

__device__ __forceinline__ void ldsm4(uint32_t& r0, uint32_t& r1, uint32_t& r2, uint32_t& r3,
                                      uint32_t addr) {
    asm volatile("ldmatrix.sync.aligned.m8n8.x4.shared.b16 {%0,%1,%2,%3}, [%4];"
                 : "=r"(r0), "=r"(r1), "=r"(r2), "=r"(r3) : "r"(addr));
}

__device__ __forceinline__ void cp16(uint32_t dst, const void* src) {
    asm volatile("cp.async.cg.shared.global [%0], [%1], 16;" :: "r"(dst), "l"(src));
}
#define CP_COMMIT() asm volatile("cp.async.commit_group;")
#define CP_WAIT0()  asm volatile("cp.async.wait_group 0;")

__device__ __forceinline__ float ex2f(float x) {
    float y;
    asm("ex2.approx.ftz.f32 %0, %1;" : "=f"(y) : "f"(x));
    return y;
}

// packed half2 exp2: one MUFU op, output is a ready fp16x2 mma fragment
__device__ __forceinline__ uint32_t h2ex2(float lo, float hi) {
    __half2 t = __floats2half2_rn(lo, hi);
    uint32_t y;
    asm("ex2.approx.f16x2 %0, %1;" : "=r"(y) : "r"(*(uint32_t*)&t));
    return y;
}
__device__ __forceinline__ uint32_t h2add(uint32_t a, uint32_t b) {
    __half2 r = __hadd2(*(__half2*)&a, *(__half2*)&b);
    return *(uint32_t*)&r;
}

// ---------------------------------------------------------------------------
// Kernel: prep — fp32->fp16 of x/Wqkv/Wproj AND RoPE tables, one launch.
// ---------------------------------------------------------------------------
#define X_N4    (M_ * C_ / 4)            // 1048576
#define WQKV_N4 (NQKV * C_ / 4)          // 196608
#define WPROJ_N4 (C_ * C_ / 4)           // 65536
#define F2H_TOTAL (X_N4 + WQKV_N4 + WPROJ_N4)
#define ROPE_N (B_ * N_ * 32)
#define PREP_TOTAL (F2H_TOTAL + ROPE_N)

__global__ void prep_kernel(const float* __restrict__ x,
                            const float* __restrict__ wqkv,
                            const float* __restrict__ wproj,
                            const float* __restrict__ times) {
    int i = blockIdx.x * 256 + threadIdx.x;
    if (i < F2H_TOTAL) {
        const float* src;
        __half* dst;
        int off;
        if (i < X_N4) { src = x; dst = g_xh; off = i; }
        else if (i < X_N4 + WQKV_N4) { src = wqkv; dst = g_Wqkvh; off = i - X_N4; }
        else { src = wproj; dst = g_Wprojh; off = i - X_N4 - WQKV_N4; }
        float4 v = ((const float4*)src)[off];
        __half2* o = (__half2*)dst;
        o[2 * off]     = __floats2half2_rn(v.x, v.y);
        o[2 * off + 1] = __floats2half2_rn(v.z, v.w);
    } else if (i < PREP_TOTAL) {
        int idx = i - F2H_TOTAL;
        int fi = idx & 31;
        int bn = idx >> 5;
        float pos = rintf(times[bn] * 30.0f);
        float inv_freq = powf(10000.0f, -(float)fi / 32.0f);
        float f = pos * inv_freq;
        float s, c;
        sincosf(f, &s, &c);
        g_cos[idx] = c;
        g_sin[idx] = s;
    }
}

// ---------------------------------------------------------------------------
// Kernel 1: QKV GEMM fp16 mma (M=8192, N=1536, K=512) + RoPE + scatter
//   128x128 tile, BK=32, 8 warps as 2(m) x 4(n), double-buffered cp.async.
//   Q is written pre-scaled by SC_LOG2E (attention softmax in exp2 domain).
// ---------------------------------------------------------------------------
__global__ __launch_bounds__(256) void gemm_qkv_h() {
    __shared__ __half As[2][128 * 40];
    __shared__ __half Bs[2][128 * 40];

    int tid = threadIdx.x;
    int w = tid >> 5, lane = tid & 31;
    int lq = lane >> 2, lr = lane & 3;
    int wm = w & 1, wn = w >> 1;
    int m0 = blockIdx.y * 128;
    int n0 = blockIdx.x * 128;

    int lrow = tid >> 1;              // 0..127
    int lk = (tid & 1) * 16;          // 0 or 16
    const __half* xg = g_xh + (size_t)(m0 + lrow) * C_ + lk;
    const __half* wg = g_Wqkvh + (size_t)(n0 + lrow) * C_ + lk;

    uint32_t asb[2] = { (uint32_t)__cvta_generic_to_shared(As[0]),
                        (uint32_t)__cvta_generic_to_shared(As[1]) };
    uint32_t bsb[2] = { (uint32_t)__cvta_generic_to_shared(Bs[0]),
                        (uint32_t)__cvta_generic_to_shared(Bs[1]) };
    uint32_t sdst = (lrow * 40 + lk) * 2;
    uint32_t afrag = ((wm * 64 + (lane & 15)) * 40 + (lane >> 4) * 8) * 2;
    uint32_t bfrag = ((wn * 32 + (lane & 15)) * 40 + (lane >> 4) * 8) * 2;

    float c[16][4];
#pragma unroll
    for (int f = 0; f < 16; ++f)
#pragma unroll
        for (int i = 0; i < 4; ++i) c[f][i] = 0.0f;

    // prologue
    cp16(asb[0] + sdst, xg);      cp16(asb[0] + sdst + 16, xg + 8);
    cp16(bsb[0] + sdst, wg);      cp16(bsb[0] + sdst + 16, wg + 8);
    CP_COMMIT();
    CP_WAIT0();
    __syncthreads();

    for (int it = 0; it < 16; ++it) {
        int buf = it & 1;
        if (it < 15) {
            int k0 = (it + 1) * 32;
            cp16(asb[buf ^ 1] + sdst, xg + k0);      cp16(asb[buf ^ 1] + sdst + 16, xg + k0 + 8);
            cp16(bsb[buf ^ 1] + sdst, wg + k0);      cp16(bsb[buf ^ 1] + sdst + 16, wg + k0 + 8);
            CP_COMMIT();
        }
#pragma unroll
        for (int ks = 0; ks < 2; ++ks) {
            uint32_t a[4][4];
#pragma unroll
            for (int mf = 0; mf < 4; ++mf)
                ldsm4(a[mf][0], a[mf][1], a[mf][2], a[mf][3],
                      asb[buf] + afrag + (mf * 16 * 40 + ks * 16) * 2);
#pragma unroll
            for (int p = 0; p < 2; ++p) {
                uint32_t b0, b1, b2, b3;
                ldsm4(b0, b1, b2, b3, bsb[buf] + bfrag + (p * 16 * 40 + ks * 16) * 2);
#pragma unroll
                for (int mf = 0; mf < 4; ++mf) {
                    mma16(c[mf * 4 + 2 * p],     a[mf][0], a[mf][1], a[mf][2], a[mf][3], b0, b2);
                    mma16(c[mf * 4 + 2 * p + 1], a[mf][0], a[mf][1], a[mf][2], a[mf][3], b1, b3);
                }
            }
        }
        if (it < 15) {
            CP_WAIT0();
            __syncthreads();
        }
    }

    // RoPE epilogue + scatter (fp32 math, fp16 store). Q pre-scaled by SC_LOG2E.
#pragma unroll
    for (int mf = 0; mf < 4; ++mf) {
#pragma unroll
        for (int half = 0; half < 2; ++half) {
            int m = m0 + wm * 64 + mf * 16 + lq + half * 8;   // global row
            int b = m >> 11;
            int n = m & 2047;
#pragma unroll
            for (int nf = 0; nf < 4; ++nf) {
                int col = n0 + wn * 32 + nf * 8 + 2 * lr;
                int s = col >> 9;
                int h = (col >> 6) & 7;
                int d = col & 63;
                float v0 = c[mf * 4 + nf][half * 2 + 0];
                float v1 = c[mf * 4 + nf][half * 2 + 1];
                if (s == 2) {
                    size_t vb = ((size_t)((b * 8 + h) * 64 + d)) * 2048 + n;
                    g_Vth[vb] = __float2half(v0);
                    g_Vth[vb + 2048] = __float2half(v1);
                } else {
                    size_t base = ((size_t)((b * 8 + h) * 2048 + n)) * 64 + d;
                    int i2 = d >> 1;
                    float sc = (s == 0) ? SC_LOG2E : 1.0f;
                    float ct = g_cos[m * 32 + i2] * sc;
                    float st = g_sin[m * 32 + i2] * sc;
                    __half2 hv = __floats2half2_rn(v0 * ct - v1 * st, v0 * st + v1 * ct);
                    if (s == 0) *(__half2*)&g_Qh[base] = hv;
                    else        *(__half2*)&g_Kh[base] = hv;
                }
            }
        }
    }
}

// ---------------------------------------------------------------------------
// Kernel 2: flash attention, fp16 mma, register-resident P, 2-stage K/V pipe.
//   Softmax in exp2 domain; P computed via ex2.approx.f16x2 (one MUFU op
//   yields a packed fp16 mma fragment); row sums via HADD2 tree.
// ---------------------------------------------------------------------------
__global__ __launch_bounds__(256, 2) void attn_h(const float* __restrict__ mask) {
    __shared__ __half Ks[2][64 * 72];
    __shared__ __half Vs[2][64 * 72];
    __shared__ float Ms[2][64];

    int tid = threadIdx.x;
    int w = tid >> 5, lane = tid & 31;
    int lq = lane >> 2, lr = lane & 3;
    int bh = blockIdx.y;
    int b = bh >> 3, h = bh & 7;
    int q0 = blockIdx.x * 128;

    const __half* Qg = g_Qh + ((size_t)bh * 2048 + q0) * 64;
    const __half* Kg = g_Kh + (size_t)bh * 2048 * 64;
    const __half* Vg = g_Vth + (size_t)bh * 64 * 2048;
    const float* maskb = mask + b * 2048;

    // Q fragments held in registers for the whole kernel
    uint32_t qf[4][4];
    int qrow = w * 16 + lq;
#pragma unroll
    for (int ks = 0; ks < 4; ++ks) {
        qf[ks][0] = *(const uint32_t*)(Qg + (size_t)qrow * 64 + ks * 16 + 2 * lr);
        qf[ks][1] = *(const uint32_t*)(Qg + (size_t)(qrow + 8) * 64 + ks * 16 + 2 * lr);
        qf[ks][2] = *(const uint32_t*)(Qg + (size_t)qrow * 64 + ks * 16 + 8 + 2 * lr);
        qf[ks][3] = *(const uint32_t*)(Qg + (size_t)(qrow + 8) * 64 + ks * 16 + 8 + 2 * lr);
    }

    uint32_t ksb[2] = { (uint32_t)__cvta_generic_to_shared(Ks[0]),
                        (uint32_t)__cvta_generic_to_shared(Ks[1]) };
    uint32_t vsb[2] = { (uint32_t)__cvta_generic_to_shared(Vs[0]),
                        (uint32_t)__cvta_generic_to_shared(Vs[1]) };
    uint32_t bfrag = ((lane & 15) * 72 + (lane >> 4) * 8) * 2;

    // cp.async chunk mapping: 512 16B-chunks per tile, 2 per thread
    int r0c = tid >> 3,         c0c = (tid & 7) * 8;
    int r1c = (tid + 256) >> 3, c1c = ((tid + 256) & 7) * 8;

    float co[8][4];
#pragma unroll
    for (int nf = 0; nf < 8; ++nf)
#pragma unroll
        for (int i = 0; i < 4; ++i) co[nf][i] = 0.0f;
    float mi0 = -INFINITY, mi1 = -INFINITY, li0 = 0.0f, li1 = 0.0f;

    // prologue: load tile 0
    {
        cp16(ksb[0] + (r0c * 72 + c0c) * 2, Kg + (size_t)r0c * 64 + c0c);
        cp16(ksb[0] + (r1c * 72 + c1c) * 2, Kg + (size_t)r1c * 64 + c1c);
        cp16(vsb[0] + (r0c * 72 + c0c) * 2, Vg + (size_t)r0c * 2048 + c0c);
        cp16(vsb[0] + (r1c * 72 + c1c) * 2, Vg + (size_t)r1c * 2048 + c1c);
        CP_COMMIT();
        if (tid < 64) Ms[0][tid] = maskb[tid] * LOG2E;
        CP_WAIT0();
        __syncthreads();
    }

    for (int kt = 0; kt < 32; ++kt) {
        int buf = kt & 1;
        if (kt < 31) {
            int nk = kt + 1;
            cp16(ksb[buf ^ 1] + (r0c * 72 + c0c) * 2, Kg + (size_t)(nk * 64 + r0c) * 64 + c0c);
            cp16(ksb[buf ^ 1] + (r1c * 72 + c1c) * 2, Kg + (size_t)(nk * 64 + r1c) * 64 + c1c);
            cp16(vsb[buf ^ 1] + (r0c * 72 + c0c) * 2, Vg + (size_t)r0c * 2048 + nk * 64 + c0c);
            cp16(vsb[buf ^ 1] + (r1c * 72 + c1c) * 2, Vg + (size_t)r1c * 2048 + nk * 64 + c1c);
            CP_COMMIT();
            if (tid < 64) Ms[buf ^ 1][tid] = maskb[nk * 64 + tid] * LOG2E;
        }

        // S = Q K^T (already in log2 domain thanks to Q pre-scale)
        float cs[8][4];
#pragma unroll
        for (int nf = 0; nf < 8; ++nf)
#pragma unroll
            for (int i = 0; i < 4; ++i) cs[nf][i] = 0.0f;

#pragma unroll
        for (int ks = 0; ks < 4; ++ks) {
#pragma unroll
            for (int p = 0; p < 4; ++p) {
                uint32_t b0, b1, b2, b3;
                ldsm4(b0, b1, b2, b3, ksb[buf] + bfrag + (p * 16 * 72 + ks * 16) * 2);
                mma16(cs[2 * p],     qf[ks][0], qf[ks][1], qf[ks][2], qf[ks][3], b0, b2);
                mma16(cs[2 * p + 1], qf[ks][0], qf[ks][1], qf[ks][2], qf[ks][3], b1, b3);
            }
        }

        // mask add + row max (fp32)
        float rm0 = -INFINITY, rm1 = -INFINITY;
#pragma unroll
        for (int nf = 0; nf < 8; ++nf) {
            float mk0 = Ms[buf][nf * 8 + 2 * lr];
            float mk1 = Ms[buf][nf * 8 + 2 * lr + 1];
            cs[nf][0] += mk0;
            cs[nf][1] += mk1;
            cs[nf][2] += mk0;
            cs[nf][3] += mk1;
            rm0 = fmaxf(rm0, fmaxf(cs[nf][0], cs[nf][1]));
            rm1 = fmaxf(rm1, fmaxf(cs[nf][2], cs[nf][3]));
        }
        rm0 = fmaxf(rm0, __shfl_xor_sync(0xffffffffu, rm0, 1));
        rm0 = fmaxf(rm0, __shfl_xor_sync(0xffffffffu, rm0, 2));
        rm1 = fmaxf(rm1, __shfl_xor_sync(0xffffffffu, rm1, 1));
        rm1 = fmaxf(rm1, __shfl_xor_sync(0xffffffffu, rm1, 2));

        float mn0 = fmaxf(mi0, rm0);
        float mn1 = fmaxf(mi1, rm1);
        float corr0 = ex2f(mi0 - mn0);
        float corr1 = ex2f(mi1 - mn1);

        // P = exp2(S - mn) directly as packed fp16 fragments (f16x2 MUFU)
        uint32_t p01[8], p23[8];
#pragma unroll
        for (int nf = 0; nf < 8; ++nf) {
            p01[nf] = h2ex2(cs[nf][0] - mn0, cs[nf][1] - mn0);
            p23[nf] = h2ex2(cs[nf][2] - mn1, cs[nf][3] - mn1);
        }

        // row sums via HADD2 tree, finish in fp32
        uint32_t t0 = h2add(h2add(h2add(p01[0], p01[1]), h2add(p01[2], p01[3])),
                            h2add(h2add(p01[4], p01[5]), h2add(p01[6], p01[7])));
        uint32_t t1 = h2add(h2add(h2add(p23[0], p23[1]), h2add(p23[2], p23[3])),
                            h2add(h2add(p23[4], p23[5]), h2add(p23[6], p23[7])));
        float2 f0 = __half22float2(*(__half2*)&t0);
        float2 f1 = __half22float2(*(__half2*)&t1);
        float sum0 = f0.x + f0.y;
        float sum1 = f1.x + f1.y;
        sum0 += __shfl_xor_sync(0xffffffffu, sum0, 1);
        sum0 += __shfl_xor_sync(0xffffffffu, sum0, 2);
        sum1 += __shfl_xor_sync(0xffffffffu, sum1, 1);
        sum1 += __shfl_xor_sync(0xffffffffu, sum1, 2);
        li0 = li0 * corr0 + sum0;
        li1 = li1 * corr1 + sum1;
        mi0 = mn0; mi1 = mn1;
#pragma unroll
        for (int nf = 0; nf < 8; ++nf) {
            co[nf][0] *= corr0; co[nf][1] *= corr0;
            co[nf][2] *= corr1; co[nf][3] *= corr1;
        }

        // O += P V — P fragments come straight from the f16x2 ex2
#pragma unroll
        for (int kc = 0; kc < 4; ++kc) {
            uint32_t pa0 = p01[2 * kc];
            uint32_t pa1 = p23[2 * kc];
            uint32_t pa2 = p01[2 * kc + 1];
            uint32_t pa3 = p23[2 * kc + 1];
#pragma unroll
            for (int p = 0; p < 4; ++p) {
                uint32_t b0, b1, b2, b3;
                ldsm4(b0, b1, b2, b3, vsb[buf] + bfrag + (p * 16 * 72 + kc * 16) * 2);
                mma16(co[2 * p],     pa0, pa1, pa2, pa3, b0, b2);
                mma16(co[2 * p + 1], pa0, pa1, pa2, pa3, b1, b3);
            }
        }

        if (kt < 31) {
            CP_WAIT0();
            __syncthreads();
        }
    }

    // normalize + write g_Oh [B,N,C] (half)
    float inv0 = 1.0f / li0;
    float inv1 = 1.0f / li1;
    int m0g = q0 + w * 16 + lq;
    int m1g = m0g + 8;
#pragma unroll
    for (int nf = 0; nf < 8; ++nf) {
        int col = h * 64 + nf * 8 + 2 * lr;
        *(__half2*)&g_Oh[((size_t)(b * 2048 + m0g)) * 512 + col] =
            __floats2half2_rn(co[nf][0] * inv0, co[nf][1] * inv0);
        *(__half2*)&g_Oh[((size_t)(b * 2048 + m1g)) * 512 + col] =
            __floats2half2_rn(co[nf][2] * inv1, co[nf][3] * inv1);
    }
}

// ---------------------------------------------------------------------------
// Kernel 3: output projection fp16 mma (M=8192, N=512, K=512) + bias, fp32 out
// ---------------------------------------------------------------------------
__global__ __launch_bounds__(256) void gemm_proj_h(const float* __restrict__ bias,
                                                   float* __restrict__ out) {
    __shared__ __half As[2][128 * 40];
    __shared__ __half Bs[2][128 * 40];

    int tid = threadIdx.x;
    int w = tid >> 5, lane = tid & 31;
    int lq = lane >> 2, lr = lane & 3;
    int wm = w & 1, wn = w >> 1;
    int m0 = blockIdx.y * 128;
    int n0 = blockIdx.x * 128;

    int lrow = tid >> 1;
    int lk = (tid & 1) * 16;
    const __half* ag = g_Oh + (size_t)(m0 + lrow) * C_ + lk;
    const __half* wg = g_Wprojh + (size_t)(n0 + lrow) * C_ + lk;

    uint32_t asb[2] = { (uint32_t)__cvta_generic_to_shared(As[0]),
                        (uint32_t)__cvta_generic_to_shared(As[1]) };
    uint32_t bsb[2] = { (uint32_t)__cvta_generic_to_shared(Bs[0]),
                        (uint32_t)__cvta_generic_to_shared(Bs[1]) };
    uint32_t sdst = (lrow * 40 + lk) * 2;
    uint32_t afrag = ((wm * 64 + (lane & 15)) * 40 + (lane >> 4) * 8) * 2;
    uint32_t bfrag = ((wn * 32 + (lane & 15)) * 40 + (lane >> 4) * 8) * 2;

    float c[16][4];
#pragma unroll
    for (int f = 0; f < 16; ++f)
#pragma unroll
        for (int i = 0; i < 4; ++i) c[f][i] = 0.0f;

    cp16(asb[0] + sdst, ag);      cp16(asb[0] + sdst + 16, ag + 8);
    cp16(bsb[0] + sdst, wg);      cp16(bsb[0] + sdst + 16, wg + 8);
    CP_COMMIT();
    CP_WAIT0();
    __syncthreads();

    for (int it = 0; it < 16; ++it) {
        int buf = it & 1;
        if (it < 15) {
            int k0 = (it + 1) * 32;
            cp16(asb[buf ^ 1] + sdst, ag + k0);      cp16(asb[buf ^ 1] + sdst + 16, ag + k0 + 8);
            cp16(bsb[buf ^ 1] + sdst, wg + k0);      cp16(bsb[buf ^ 1] + sdst + 16, wg + k0 + 8);
            CP_COMMIT();
        }
#pragma unroll
        for (int ks = 0; ks < 2; ++ks) {
            uint32_t a[4][4];
#pragma unroll
            for (int mf = 0; mf < 4; ++mf)
                ldsm4(a[mf][0], a[mf][1], a[mf][2], a[mf][3],
                      asb[buf] + afrag + (mf * 16 * 40 + ks * 16) * 2);
#pragma unroll
            for (int p = 0; p < 2; ++p) {
                uint32_t b0, b1, b2, b3;
                ldsm4(b0, b1, b2, b3, bsb[buf] + bfrag + (p * 16 * 40 + ks * 16) * 2);
#pragma unroll
                for (int mf = 0; mf < 4; ++mf) {
                    mma16(c[mf * 4 + 2 * p],     a[mf][0], a[mf][1], a[mf][2], a[mf][3], b0, b2);
                    mma16(c[mf * 4 + 2 * p + 1], a[mf][0], a[mf][1], a[mf][2], a[mf][3], b1, b3);
                }
            }
        }
        if (it < 15) {
            CP_WAIT0();
            __syncthreads();
        }
    }

#pragma unroll
    for (int mf = 0; mf < 4; ++mf) {
#pragma unroll
        for (int half = 0; half < 2; ++half) {
            int m = m0 + wm * 64 + mf * 16 + lq + half * 8;
#pragma unroll
            for (int nf = 0; nf < 4; ++nf) {
                int col = n0 + wn * 32 + nf * 8 + 2 * lr;
                float v0 = c[mf * 4 + nf][half * 2 + 0] + bias[col];
                float v1 = c[mf * 4 + nf][half * 2 + 1] + bias[col + 1];
                *(float2*)&out[(size_t)m * 512 + col] = make_float2(v0, v1);
            }
        }
    }
}

// ---------------------------------------------------------------------------
extern "C" void kernel_launch(void* const* d_in, const int* in_sizes, int n_in,
                              void* d_out, int out_size) {
    const float* x     = (const float*)d_in[0];
    const float* mask  = (const float*)d_in[1];
    const float* times = (const float*)d_in[2];
    const float* Wqkv  = (const float*)d_in[3];
    const float* Wproj = (const float*)d_in[4];
    const float* bproj = (const float*)d_in[5];
    (void)in_sizes; (void)n_in; (void)out_size;   // num_cls_token == 0 (fixed input)

    prep_kernel<<<(PREP_TOTAL + 255) / 256, 256>>>(x, Wqkv, Wproj, times);

    gemm_qkv_h<<<dim3(NQKV / 128, M_ / 128), 256>>>();
    attn_h<<<dim3(N_ / 128, B_ * H_), 256>>>(mask);
    gemm_proj_h<<<dim3(C_ / 128, M_ / 128), 256>>>(bproj, (float*)d_out);
}

// round 10
// speedup vs baseline: 5.7213x; 1.0133x over previous
#include <cuda_runtime.h>
#include <cuda_fp16.h>
#include <math.h>
#include <stdint.h>

// Problem constants
#define B_ 4
#define N_ 2048
#define C_ 512
#define H_ 8
#define DH 64
#define M_ (B_ * N_)          // 8192
#define NQKV (3 * C_)         // 1536

#define SC_LOG2E 0.18033688011112042f   // 0.125 * log2(e)
#define LOG2E    1.4426950408889634f

// Scratch (device globals; no allocation allowed)
__device__ __half g_xh[M_ * C_];
__device__ __half g_Wqkvh[NQKV * C_];
__device__ __half g_Wprojh[C_ * C_];
__device__ __half g_Qh[B_ * H_ * N_ * DH];    // pre-scaled by SC_LOG2E
__device__ __half g_Kh[B_ * H_ * N_ * DH];
__device__ __half g_Vth[B_ * H_ * DH * N_];   // V transposed: [b,h,d,n]
__device__ __half g_Oh[M_ * C_];
__device__ float g_cos[B_ * N_ * (DH / 2)];
__device__ float g_sin[B_ * N_ * (DH / 2)];

// ---------------------------------------------------------------------------
// helpers
// ---------------------------------------------------------------------------
__device__ __forceinline__ void mma16(float* c,
                                      uint32_t a0, uint32_t a1, uint32_t a2, uint32_t a3,
                                      uint32_t b0, uint32_t b1) {
    asm volatile(
        "mma.sync.aligned.m16n8k16.row.col.f32.f16.f16.f32 "
        "{%0,%1,%2,%3},{%4,%5,%6,%7},{%8,%9},{%0,%1,%2,%3};"
        : "+f"(c[0]), "+f"(c[1]), "+f"(c[2]), "+f"(c[3])
        : "r"(a0), "r"(a1), "r"(a2), "r"(a3), "r"(b0), "r"(b1));
}

__device__ __forceinline__ void ldsm4(uint32_t& r0, uint32_t& r1, uint32_t& r2, uint32_t& r3,
                                      uint32_t addr) {
    asm volatile("ldmatrix.sync.aligned.m8n8.x4.shared.b16 {%0,%1,%2,%3}, [%4];"
                 : "=r"(r0), "=r"(r1), "=r"(r2), "=r"(r3) : "r"(addr));
}

__device__ __forceinline__ void cp16(uint32_t dst, const void* src) {
    asm volatile("cp.async.cg.shared.global [%0], [%1], 16;" :: "r"(dst), "l"(src));
}
#define CP_COMMIT() asm volatile("cp.async.commit_group;")
#define CP_WAIT0()  asm volatile("cp.async.wait_group 0;")

__device__ __forceinline__ float ex2f(float x) {
    float y;
    asm("ex2.approx.ftz.f32 %0, %1;" : "=f"(y) : "f"(x));
    return y;
}

// packed half2 exp2: one MUFU op, output is a ready fp16x2 mma fragment
__device__ __forceinline__ uint32_t h2ex2(float lo, float hi) {
    __half2 t = __floats2half2_rn(lo, hi);
    uint32_t y;
    asm("ex2.approx.f16x2 %0, %1;" : "=r"(y) : "r"(*(uint32_t*)&t));
    return y;
}
__device__ __forceinline__ uint32_t h2add(uint32_t a, uint32_t b) {
    __half2 r = __hadd2(*(__half2*)&a, *(__half2*)&b);
    return *(uint32_t*)&r;
}

// ---------------------------------------------------------------------------
// Kernel: prep — fp32->fp16 of x/Wqkv/Wproj AND RoPE tables, one launch.
// ---------------------------------------------------------------------------
#define X_N4    (M_ * C_ / 4)            // 1048576
#define WQKV_N4 (NQKV * C_ / 4)          // 196608
#define WPROJ_N4 (C_ * C_ / 4)           // 65536
#define F2H_TOTAL (X_N4 + WQKV_N4 + WPROJ_N4)
#define ROPE_N (B_ * N_ * 32)
#define PREP_TOTAL (F2H_TOTAL + ROPE_N)

__global__ void prep_kernel(const float* __restrict__ x,
                            const float* __restrict__ wqkv,
                            const float* __restrict__ wproj,
                            const float* __restrict__ times) {
    int i = blockIdx.x * 256 + threadIdx.x;
    if (i < F2H_TOTAL) {
        const float* src;
        __half* dst;
        int off;
        if (i < X_N4) { src = x; dst = g_xh; off = i; }
        else if (i < X_N4 + WQKV_N4) { src = wqkv; dst = g_Wqkvh; off = i - X_N4; }
        else { src = wproj; dst = g_Wprojh; off = i - X_N4 - WQKV_N4; }
        float4 v = ((const float4*)src)[off];
        __half2* o = (__half2*)dst;
        o[2 * off]     = __floats2half2_rn(v.x, v.y);
        o[2 * off + 1] = __floats2half2_rn(v.z, v.w);
    } else if (i < PREP_TOTAL) {
        int idx = i - F2H_TOTAL;
        int fi = idx & 31;
        int bn = idx >> 5;
        float pos = rintf(times[bn] * 30.0f);
        float inv_freq = powf(10000.0f, -(float)fi / 32.0f);
        float f = pos * inv_freq;
        float s, c;
        sincosf(f, &s, &c);
        g_cos[idx] = c;
        g_sin[idx] = s;
    }
}

// ---------------------------------------------------------------------------
// Kernel 1: QKV GEMM fp16 mma (M=8192, N=1536, K=512) + RoPE + scatter
// ---------------------------------------------------------------------------
__global__ __launch_bounds__(256) void gemm_qkv_h() {
    __shared__ __half As[2][128 * 40];
    __shared__ __half Bs[2][128 * 40];

    int tid = threadIdx.x;
    int w = tid >> 5, lane = tid & 31;
    int lq = lane >> 2, lr = lane & 3;
    int wm = w & 1, wn = w >> 1;
    int m0 = blockIdx.y * 128;
    int n0 = blockIdx.x * 128;

    int lrow = tid >> 1;              // 0..127
    int lk = (tid & 1) * 16;          // 0 or 16
    const __half* xg = g_xh + (size_t)(m0 + lrow) * C_ + lk;
    const __half* wg = g_Wqkvh + (size_t)(n0 + lrow) * C_ + lk;

    uint32_t asb[2] = { (uint32_t)__cvta_generic_to_shared(As[0]),
                        (uint32_t)__cvta_generic_to_shared(As[1]) };
    uint32_t bsb[2] = { (uint32_t)__cvta_generic_to_shared(Bs[0]),
                        (uint32_t)__cvta_generic_to_shared(Bs[1]) };
    uint32_t sdst = (lrow * 40 + lk) * 2;
    uint32_t afrag = ((wm * 64 + (lane & 15)) * 40 + (lane >> 4) * 8) * 2;
    uint32_t bfrag = ((wn * 32 + (lane & 15)) * 40 + (lane >> 4) * 8) * 2;

    float c[16][4];
#pragma unroll
    for (int f = 0; f < 16; ++f)
#pragma unroll
        for (int i = 0; i < 4; ++i) c[f][i] = 0.0f;

    cp16(asb[0] + sdst, xg);      cp16(asb[0] + sdst + 16, xg + 8);
    cp16(bsb[0] + sdst, wg);      cp16(bsb[0] + sdst + 16, wg + 8);
    CP_COMMIT();
    CP_WAIT0();
    __syncthreads();

    for (int it = 0; it < 16; ++it) {
        int buf = it & 1;
        if (it < 15) {
            int k0 = (it + 1) * 32;
            cp16(asb[buf ^ 1] + sdst, xg + k0);      cp16(asb[buf ^ 1] + sdst + 16, xg + k0 + 8);
            cp16(bsb[buf ^ 1] + sdst, wg + k0);      cp16(bsb[buf ^ 1] + sdst + 16, wg + k0 + 8);
            CP_COMMIT();
        }
#pragma unroll
        for (int ks = 0; ks < 2; ++ks) {
            uint32_t a[4][4];
#pragma unroll
            for (int mf = 0; mf < 4; ++mf)
                ldsm4(a[mf][0], a[mf][1], a[mf][2], a[mf][3],
                      asb[buf] + afrag + (mf * 16 * 40 + ks * 16) * 2);
#pragma unroll
            for (int p = 0; p < 2; ++p) {
                uint32_t b0, b1, b2, b3;
                ldsm4(b0, b1, b2, b3, bsb[buf] + bfrag + (p * 16 * 40 + ks * 16) * 2);
#pragma unroll
                for (int mf = 0; mf < 4; ++mf) {
                    mma16(c[mf * 4 + 2 * p],     a[mf][0], a[mf][1], a[mf][2], a[mf][3], b0, b2);
                    mma16(c[mf * 4 + 2 * p + 1], a[mf][0], a[mf][1], a[mf][2], a[mf][3], b1, b3);
                }
            }
        }
        if (it < 15) {
            CP_WAIT0();
            __syncthreads();
        }
    }

    // RoPE epilogue + scatter (fp32 math, fp16 store). Q pre-scaled by SC_LOG2E.
#pragma unroll
    for (int mf = 0; mf < 4; ++mf) {
#pragma unroll
        for (int half = 0; half < 2; ++half) {
            int m = m0 + wm * 64 + mf * 16 + lq + half * 8;   // global row
            int b = m >> 11;
            int n = m & 2047;
#pragma unroll
            for (int nf = 0; nf < 4; ++nf) {
                int col = n0 + wn * 32 + nf * 8 + 2 * lr;
                int s = col >> 9;
                int h = (col >> 6) & 7;
                int d = col & 63;
                float v0 = c[mf * 4 + nf][half * 2 + 0];
                float v1 = c[mf * 4 + nf][half * 2 + 1];
                if (s == 2) {
                    size_t vb = ((size_t)((b * 8 + h) * 64 + d)) * 2048 + n;
                    g_Vth[vb] = __float2half(v0);
                    g_Vth[vb + 2048] = __float2half(v1);
                } else {
                    size_t base = ((size_t)((b * 8 + h) * 2048 + n)) * 64 + d;
                    int i2 = d >> 1;
                    float sc = (s == 0) ? SC_LOG2E : 1.0f;
                    float ct = g_cos[m * 32 + i2] * sc;
                    float st = g_sin[m * 32 + i2] * sc;
                    __half2 hv = __floats2half2_rn(v0 * ct - v1 * st, v0 * st + v1 * ct);
                    if (s == 0) *(__half2*)&g_Qh[base] = hv;
                    else        *(__half2*)&g_Kh[base] = hv;
                }
            }
        }
    }
}

// ---------------------------------------------------------------------------
// Kernel 2: flash attention. 4 warps x 32 q-rows (two A-frag blocks each):
//   every K/V B-fragment ldsm feeds 4 MMAs -> LDS amplification halved.
//   128 threads/CTA, 2 CTA/SM guaranteed (<=255 regs). exp2-domain softmax.
// ---------------------------------------------------------------------------
__global__ __launch_bounds__(128) void attn_h(const float* __restrict__ mask) {
    __shared__ __half Ks[2][64 * 72];
    __shared__ __half Vs[2][64 * 72];
    __shared__ float Ms[2][64];

    int tid = threadIdx.x;
    int w = tid >> 5, lane = tid & 31;
    int lq = lane >> 2, lr = lane & 3;
    int bh = blockIdx.y;
    int b = bh >> 3, h = bh & 7;
    int q0 = blockIdx.x * 128;

    const __half* Qg = g_Qh + ((size_t)bh * 2048 + q0) * 64;
    const __half* Kg = g_Kh + (size_t)bh * 2048 * 64;
    const __half* Vg = g_Vth + (size_t)bh * 64 * 2048;
    const float* maskb = mask + b * 2048;

    // Q fragments: 2 row-blocks x 4 ks x 4 regs (rows w*32 + blk*16 + lq/+8)
    uint32_t qf[2][4][4];
#pragma unroll
    for (int blk = 0; blk < 2; ++blk) {
        int qrow = w * 32 + blk * 16 + lq;
#pragma unroll
        for (int ks = 0; ks < 4; ++ks) {
            qf[blk][ks][0] = *(const uint32_t*)(Qg + (size_t)qrow * 64 + ks * 16 + 2 * lr);
            qf[blk][ks][1] = *(const uint32_t*)(Qg + (size_t)(qrow + 8) * 64 + ks * 16 + 2 * lr);
            qf[blk][ks][2] = *(const uint32_t*)(Qg + (size_t)qrow * 64 + ks * 16 + 8 + 2 * lr);
            qf[blk][ks][3] = *(const uint32_t*)(Qg + (size_t)(qrow + 8) * 64 + ks * 16 + 8 + 2 * lr);
        }
    }

    uint32_t ksb[2] = { (uint32_t)__cvta_generic_to_shared(Ks[0]),
                        (uint32_t)__cvta_generic_to_shared(Ks[1]) };
    uint32_t vsb[2] = { (uint32_t)__cvta_generic_to_shared(Vs[0]),
                        (uint32_t)__cvta_generic_to_shared(Vs[1]) };
    uint32_t bfrag = ((lane & 15) * 72 + (lane >> 4) * 8) * 2;

    // cp.async: 512 16B-chunks per tile, 4 per thread (128 threads)
    int rc[4], cc[4];
#pragma unroll
    for (int j = 0; j < 4; ++j) {
        int q = j * 128 + tid;
        rc[j] = q >> 3;
        cc[j] = (q & 7) * 8;
    }

    float co[2][8][4];
#pragma unroll
    for (int blk = 0; blk < 2; ++blk)
#pragma unroll
        for (int nf = 0; nf < 8; ++nf)
#pragma unroll
            for (int i = 0; i < 4; ++i) co[blk][nf][i] = 0.0f;
    float mi[4] = { -INFINITY, -INFINITY, -INFINITY, -INFINITY };
    float li[4] = { 0.0f, 0.0f, 0.0f, 0.0f };

    // prologue: load tile 0
    {
#pragma unroll
        for (int j = 0; j < 4; ++j) {
            cp16(ksb[0] + (rc[j] * 72 + cc[j]) * 2, Kg + (size_t)rc[j] * 64 + cc[j]);
            cp16(vsb[0] + (rc[j] * 72 + cc[j]) * 2, Vg + (size_t)rc[j] * 2048 + cc[j]);
        }
        CP_COMMIT();
        if (tid < 64) Ms[0][tid] = maskb[tid] * LOG2E;
        CP_WAIT0();
        __syncthreads();
    }

    for (int kt = 0; kt < 32; ++kt) {
        int buf = kt & 1;
        if (kt < 31) {
            int nk = kt + 1;
#pragma unroll
            for (int j = 0; j < 4; ++j) {
                cp16(ksb[buf ^ 1] + (rc[j] * 72 + cc[j]) * 2,
                     Kg + (size_t)(nk * 64 + rc[j]) * 64 + cc[j]);
                cp16(vsb[buf ^ 1] + (rc[j] * 72 + cc[j]) * 2,
                     Vg + (size_t)rc[j] * 2048 + nk * 64 + cc[j]);
            }
            CP_COMMIT();
            if (tid < 64) Ms[buf ^ 1][tid] = maskb[nk * 64 + tid] * LOG2E;
        }

        // S = Q K^T for both row blocks; each K b-frag ldsm feeds 4 MMAs
        float cs[2][8][4];
#pragma unroll
        for (int blk = 0; blk < 2; ++blk)
#pragma unroll
            for (int nf = 0; nf < 8; ++nf)
#pragma unroll
                for (int i = 0; i < 4; ++i) cs[blk][nf][i] = 0.0f;

#pragma unroll
        for (int ks = 0; ks < 4; ++ks) {
#pragma unroll
            for (int p = 0; p < 4; ++p) {
                uint32_t b0, b1, b2, b3;
                ldsm4(b0, b1, b2, b3, ksb[buf] + bfrag + (p * 16 * 72 + ks * 16) * 2);
#pragma unroll
                for (int blk = 0; blk < 2; ++blk) {
                    mma16(cs[blk][2 * p],     qf[blk][ks][0], qf[blk][ks][1],
                          qf[blk][ks][2], qf[blk][ks][3], b0, b2);
                    mma16(cs[blk][2 * p + 1], qf[blk][ks][0], qf[blk][ks][1],
                          qf[blk][ks][2], qf[blk][ks][3], b1, b3);
                }
            }
        }

        // mask add + row max (cols identical across blocks)
        float rm[4] = { -INFINITY, -INFINITY, -INFINITY, -INFINITY };
#pragma unroll
        for (int nf = 0; nf < 8; ++nf) {
            float mk0 = Ms[buf][nf * 8 + 2 * lr];
            float mk1 = Ms[buf][nf * 8 + 2 * lr + 1];
#pragma unroll
            for (int blk = 0; blk < 2; ++blk) {
                cs[blk][nf][0] += mk0;
                cs[blk][nf][1] += mk1;
                cs[blk][nf][2] += mk0;
                cs[blk][nf][3] += mk1;
                rm[2 * blk]     = fmaxf(rm[2 * blk],     fmaxf(cs[blk][nf][0], cs[blk][nf][1]));
                rm[2 * blk + 1] = fmaxf(rm[2 * blk + 1], fmaxf(cs[blk][nf][2], cs[blk][nf][3]));
            }
        }
#pragma unroll
        for (int r = 0; r < 4; ++r) {
            rm[r] = fmaxf(rm[r], __shfl_xor_sync(0xffffffffu, rm[r], 1));
            rm[r] = fmaxf(rm[r], __shfl_xor_sync(0xffffffffu, rm[r], 2));
        }

        float mn[4], corr[4];
#pragma unroll
        for (int r = 0; r < 4; ++r) {
            mn[r] = fmaxf(mi[r], rm[r]);
            corr[r] = ex2f(mi[r] - mn[r]);
        }

        // P = exp2(S - mn) as packed fp16 fragments
        uint32_t p01[2][8], p23[2][8];
#pragma unroll
        for (int blk = 0; blk < 2; ++blk)
#pragma unroll
            for (int nf = 0; nf < 8; ++nf) {
                p01[blk][nf] = h2ex2(cs[blk][nf][0] - mn[2 * blk],
                                     cs[blk][nf][1] - mn[2 * blk]);
                p23[blk][nf] = h2ex2(cs[blk][nf][2] - mn[2 * blk + 1],
                                     cs[blk][nf][3] - mn[2 * blk + 1]);
            }

        // row sums via HADD2 trees
        float sum[4];
#pragma unroll
        for (int blk = 0; blk < 2; ++blk) {
            uint32_t t0 = h2add(h2add(h2add(p01[blk][0], p01[blk][1]),
                                      h2add(p01[blk][2], p01[blk][3])),
                                h2add(h2add(p01[blk][4], p01[blk][5]),
                                      h2add(p01[blk][6], p01[blk][7])));
            uint32_t t1 = h2add(h2add(h2add(p23[blk][0], p23[blk][1]),
                                      h2add(p23[blk][2], p23[blk][3])),
                                h2add(h2add(p23[blk][4], p23[blk][5]),
                                      h2add(p23[blk][6], p23[blk][7])));
            float2 f0 = __half22float2(*(__half2*)&t0);
            float2 f1 = __half22float2(*(__half2*)&t1);
            sum[2 * blk]     = f0.x + f0.y;
            sum[2 * blk + 1] = f1.x + f1.y;
        }
#pragma unroll
        for (int r = 0; r < 4; ++r) {
            sum[r] += __shfl_xor_sync(0xffffffffu, sum[r], 1);
            sum[r] += __shfl_xor_sync(0xffffffffu, sum[r], 2);
            li[r] = li[r] * corr[r] + sum[r];
            mi[r] = mn[r];
        }
#pragma unroll
        for (int blk = 0; blk < 2; ++blk)
#pragma unroll
            for (int nf = 0; nf < 8; ++nf) {
                co[blk][nf][0] *= corr[2 * blk];
                co[blk][nf][1] *= corr[2 * blk];
                co[blk][nf][2] *= corr[2 * blk + 1];
                co[blk][nf][3] *= corr[2 * blk + 1];
            }

        // O += P V — each V b-frag ldsm feeds 4 MMAs
#pragma unroll
        for (int kc = 0; kc < 4; ++kc) {
#pragma unroll
            for (int p = 0; p < 4; ++p) {
                uint32_t b0, b1, b2, b3;
                ldsm4(b0, b1, b2, b3, vsb[buf] + bfrag + (p * 16 * 72 + kc * 16) * 2);
#pragma unroll
                for (int blk = 0; blk < 2; ++blk) {
                    mma16(co[blk][2 * p],     p01[blk][2 * kc], p23[blk][2 * kc],
                          p01[blk][2 * kc + 1], p23[blk][2 * kc + 1], b0, b2);
                    mma16(co[blk][2 * p + 1], p01[blk][2 * kc], p23[blk][2 * kc],
                          p01[blk][2 * kc + 1], p23[blk][2 * kc + 1], b1, b3);
                }
            }
        }

        if (kt < 31) {
            CP_WAIT0();
            __syncthreads();
        }
    }

    // normalize + write g_Oh [B,N,C] (half)
#pragma unroll
    for (int blk = 0; blk < 2; ++blk) {
        float inv0 = 1.0f / li[2 * blk];
        float inv1 = 1.0f / li[2 * blk + 1];
        int m0g = q0 + w * 32 + blk * 16 + lq;
        int m1g = m0g + 8;
#pragma unroll
        for (int nf = 0; nf < 8; ++nf) {
            int col = h * 64 + nf * 8 + 2 * lr;
            *(__half2*)&g_Oh[((size_t)(b * 2048 + m0g)) * 512 + col] =
                __floats2half2_rn(co[blk][nf][0] * inv0, co[blk][nf][1] * inv0);
            *(__half2*)&g_Oh[((size_t)(b * 2048 + m1g)) * 512 + col] =
                __floats2half2_rn(co[blk][nf][2] * inv1, co[blk][nf][3] * inv1);
        }
    }
}

// ---------------------------------------------------------------------------
// Kernel 3: output projection fp16 mma (M=8192, N=512, K=512) + bias, fp32 out
// ---------------------------------------------------------------------------
__global__ __launch_bounds__(256) void gemm_proj_h(const float* __restrict__ bias,
                                                   float* __restrict__ out) {
    __shared__ __half As[2][128 * 40];
    __shared__ __half Bs[2][128 * 40];

    int tid = threadIdx.x;
    int w = tid >> 5, lane = tid & 31;
    int lq = lane >> 2, lr = lane & 3;
    int wm = w & 1, wn = w >> 1;
    int m0 = blockIdx.y * 128;
    int n0 = blockIdx.x * 128;

    int lrow = tid >> 1;
    int lk = (tid & 1) * 16;
    const __half* ag = g_Oh + (size_t)(m0 + lrow) * C_ + lk;
    const __half* wg = g_Wprojh + (size_t)(n0 + lrow) * C_ + lk;

    uint32_t asb[2] = { (uint32_t)__cvta_generic_to_shared(As[0]),
                        (uint32_t)__cvta_generic_to_shared(As[1]) };
    uint32_t bsb[2] = { (uint32_t)__cvta_generic_to_shared(Bs[0]),
                        (uint32_t)__cvta_generic_to_shared(Bs[1]) };
    uint32_t sdst = (lrow * 40 + lk) * 2;
    uint32_t afrag = ((wm * 64 + (lane & 15)) * 40 + (lane >> 4) * 8) * 2;
    uint32_t bfrag = ((wn * 32 + (lane & 15)) * 40 + (lane >> 4) * 8) * 2;

    float c[16][4];
#pragma unroll
    for (int f = 0; f < 16; ++f)
#pragma unroll
        for (int i = 0; i < 4; ++i) c[f][i] = 0.0f;

    cp16(asb[0] + sdst, ag);      cp16(asb[0] + sdst + 16, ag + 8);
    cp16(bsb[0] + sdst, wg);      cp16(bsb[0] + sdst + 16, wg + 8);
    CP_COMMIT();
    CP_WAIT0();
    __syncthreads();

    for (int it = 0; it < 16; ++it) {
        int buf = it & 1;
        if (it < 15) {
            int k0 = (it + 1) * 32;
            cp16(asb[buf ^ 1] + sdst, ag + k0);      cp16(asb[buf ^ 1] + sdst + 16, ag + k0 + 8);
            cp16(bsb[buf ^ 1] + sdst, wg + k0);      cp16(bsb[buf ^ 1] + sdst + 16, wg + k0 + 8);
            CP_COMMIT();
        }
#pragma unroll
        for (int ks = 0; ks < 2; ++ks) {
            uint32_t a[4][4];
#pragma unroll
            for (int mf = 0; mf < 4; ++mf)
                ldsm4(a[mf][0], a[mf][1], a[mf][2], a[mf][3],
                      asb[buf] + afrag + (mf * 16 * 40 + ks * 16) * 2);
#pragma unroll
            for (int p = 0; p < 2; ++p) {
                uint32_t b0, b1, b2, b3;
                ldsm4(b0, b1, b2, b3, bsb[buf] + bfrag + (p * 16 * 40 + ks * 16) * 2);
#pragma unroll
                for (int mf = 0; mf < 4; ++mf) {
                    mma16(c[mf * 4 + 2 * p],     a[mf][0], a[mf][1], a[mf][2], a[mf][3], b0, b2);
                    mma16(c[mf * 4 + 2 * p + 1], a[mf][0], a[mf][1], a[mf][2], a[mf][3], b1, b3);
                }
            }
        }
        if (it < 15) {
            CP_WAIT0();
            __syncthreads();
        }
    }

#pragma unroll
    for (int mf = 0; mf < 4; ++mf) {
#pragma unroll
        for (int half = 0; half < 2; ++half) {
            int m = m0 + wm * 64 + mf * 16 + lq + half * 8;
#pragma unroll
            for (int nf = 0; nf < 4; ++nf) {
                int col = n0 + wn * 32 + nf * 8 + 2 * lr;
                float v0 = c[mf * 4 + nf][half * 2 + 0] + bias[col];
                float v1 = c[mf * 4 + nf][half * 2 + 1] + bias[col + 1];
                *(float2*)&out[(size_t)m * 512 + col] = make_float2(v0, v1);
            }
        }
    }
}

// ---------------------------------------------------------------------------
extern "C" void kernel_launch(void* const* d_in, const int* in_sizes, int n_in,
                              void* d_out, int out_size) {
    const float* x     = (const float*)d_in[0];
    const float* mask  = (const float*)d_in[1];
    const float* times = (const float*)d_in[2];
    const float* Wqkv  = (const float*)d_in[3];
    const float* Wproj = (const float*)d_in[4];
    const float* bproj = (const float*)d_in[5];
    (void)in_sizes; (void)n_in; (void)out_size;   // num_cls_token == 0 (fixed input)

    prep_kernel<<<(PREP_TOTAL + 255) / 256, 256>>>(x, Wqkv, Wproj, times);

    gemm_qkv_h<<<dim3(NQKV / 128, M_ / 128), 256>>>();
    attn_h<<<dim3(N_ / 128, B_ * H_), 128>>>(mask);
    gemm_proj_h<<<dim3(C_ / 128, M_ / 128), 256>>>(bproj, (float*)d_out);
}